// round 4
// baseline (speedup 1.0000x reference)
#include <cuda_runtime.h>
#include <math.h>

#define Bv    8
#define Tv    512
#define Cv    512
#define Hv    8
#define DHv   64
#define Lv    2
#define Vv    512
#define FFv   2048
#define STEPS 4
#define MALL  (Bv*Tv)
#define SCALE 0.125f

#define BM 128
#define BN 64
#define BK 32
#define ASTR 36
#define BSTR 36
#define SMEM_BYTES ((2*BM*ASTR + 2*BN*BSTR)*4)

#define QROWS 128
#define KTILE 64
#define DSTR  68
#define ATT_SMEM_BYTES ((2*QROWS*DSTR + 4*KTILE*DSTR)*4)

__device__ float g_x [MALL*Cv];
__device__ float g_xn[MALL*Cv];
__device__ float g_q [MALL*Cv];
__device__ float g_k [MALL*Cv];
__device__ float g_v [MALL*Cv];
__device__ float g_y [MALL*Cv];
__device__ float g_h [MALL*FFv];

__device__ __forceinline__ unsigned f2tf(float f)
{
    unsigned u;
    asm("cvt.rna.tf32.f32 %0, %1;" : "=r"(u) : "f"(f));
    return u;
}

__device__ __forceinline__ void mma8(float acc[4],
                                     unsigned a0, unsigned a1, unsigned a2, unsigned a3,
                                     unsigned b0, unsigned b1)
{
    asm volatile(
        "mma.sync.aligned.m16n8k8.row.col.f32.tf32.tf32.f32 "
        "{%0,%1,%2,%3}, {%4,%5,%6,%7}, {%8,%9}, {%0,%1,%2,%3};\n"
        : "+f"(acc[0]), "+f"(acc[1]), "+f"(acc[2]), "+f"(acc[3])
        : "r"(a0), "r"(a1), "r"(a2), "r"(a3), "r"(b0), "r"(b1));
}

__global__ void embed_k(const int* __restrict__ idx,
                        const float* __restrict__ tok,
                        const float* __restrict__ pos,
                        float* __restrict__ x)
{
    int i = blockIdx.x * 256 + threadIdx.x;
    int c  = i & (Cv - 1);
    int bt = i >> 9;
    int t  = bt & (Tv - 1);
    x[i] = tok[idx[bt] * Cv + c] + pos[t * Cv + c];
}

__device__ __forceinline__ float block_sum(float v, float* red)
{
    for (int o = 16; o > 0; o >>= 1) v += __shfl_xor_sync(0xffffffffu, v, o);
    int warp = threadIdx.x >> 5, lane = threadIdx.x & 31;
    if (lane == 0) red[warp] = v;
    __syncthreads();
    if (warp == 0) {
        float s = (lane < 8) ? red[lane] : 0.f;
        for (int o = 4; o > 0; o >>= 1) s += __shfl_xor_sync(0xffffffffu, s, o);
        if (lane == 0) red[0] = s;
    }
    __syncthreads();
    float r = red[0];
    __syncthreads();
    return r;
}

__global__ __launch_bounds__(256) void ln_k(const float* __restrict__ x,
                                            const float* __restrict__ g,
                                            const float* __restrict__ b,
                                            float* __restrict__ o)
{
    __shared__ float red[32];
    long row = blockIdx.x;
    const float* xr = x + row * Cv;
    int c0 = threadIdx.x, c1 = threadIdx.x + 256;
    float v0 = xr[c0], v1 = xr[c1];
    float mu = block_sum(v0 + v1, red) * (1.f / Cv);
    float d0 = v0 - mu, d1 = v1 - mu;
    float var = block_sum(d0 * d0 + d1 * d1, red) * (1.f / Cv);
    float inv = rsqrtf(var + 1e-5f);
    float* orow = o + row * Cv;
    orow[c0] = d0 * inv * g[c0] + b[c0];
    orow[c1] = d1 * inv * g[c1] + b[c1];
}

// ---- tf32 GEMM, permuted smem, vector fragment loads ----
// C = act(A @ B + bias + res). A[M,K] row-major, B[K,N] row-major.
template <bool GELU_ACT>
__global__ __launch_bounds__(256, 2) void gemm_tc(
    const float* __restrict__ A, int lda,
    const float* __restrict__ Bm, int ldb,
    const float* __restrict__ bias,
    const float* __restrict__ res,
    float* __restrict__ Cm, int ldc,
    int K)
{
    extern __shared__ unsigned sm_[];
    unsigned* As = sm_;                       // [2][BM][ASTR]
    unsigned* Bs = sm_ + 2 * BM * ASTR;       // [2][BN][BSTR]

    const int tid  = threadIdx.x;
    const int lane = tid & 31;
    const int wid  = tid >> 5;
    const int mWarp = (wid >> 1) * 32;
    const int nWarp = (wid & 1) * 32;
    const int rowBase = blockIdx.y * BM;
    const int colBase = blockIdx.x * BN;
    const int r  = lane >> 2;
    const int cq = lane & 3;

    const int arow  = tid & 127;
    const int khalf = (tid >> 7) * 16;
    const int bn  = tid & 63;
    const int bk8 = (tid >> 6) * 8;

    float acc[2][4][4];
#pragma unroll
    for (int mi = 0; mi < 2; mi++)
#pragma unroll
        for (int ni = 0; ni < 4; ni++)
#pragma unroll
            for (int t = 0; t < 4; t++) acc[mi][ni][t] = 0.f;

    const int KT = K / BK;
    float4 ra[4];
    float rbv[8];
    const float* aptr = A + (long)(rowBase + arow) * lda + khalf;
    const float* bptr = Bm + colBase + bn;

#pragma unroll
    for (int u = 0; u < 4; u++) ra[u] = *(const float4*)(aptr + 4 * u);
#pragma unroll
    for (int j = 0; j < 8; j++) rbv[j] = bptr[(long)(bk8 + j) * ldb];
    {
        unsigned* ad = As + arow * ASTR + (khalf >> 2);
        const float* fr = (const float*)ra;
#pragma unroll
        for (int e = 0; e < 4; e++) {
            uint4 s;
            s.x = f2tf(fr[e]); s.y = f2tf(fr[4 + e]);
            s.z = f2tf(fr[8 + e]); s.w = f2tf(fr[12 + e]);
            *(uint4*)(ad + e * 8) = s;
        }
        unsigned* bd = Bs + bn * BSTR + (bk8 >> 2);
#pragma unroll
        for (int e = 0; e < 4; e++) {
            uint2 s;
            s.x = f2tf(rbv[e]); s.y = f2tf(rbv[e + 4]);
            *(uint2*)(bd + e * 8) = s;
        }
    }
    __syncthreads();

    for (int kt = 0; kt < KT; kt++) {
        const int buf = kt & 1;
        const bool hasNext = (kt + 1 < KT);
        if (hasNext) {
            const int k0 = (kt + 1) * BK;
#pragma unroll
            for (int u = 0; u < 4; u++) ra[u] = *(const float4*)(aptr + k0 + 4 * u);
#pragma unroll
            for (int j = 0; j < 8; j++) rbv[j] = bptr[(long)(k0 + bk8 + j) * ldb];
        }

        const unsigned* Ab = As + buf * BM * ASTR;
        const unsigned* Bb = Bs + buf * BN * BSTR;
#pragma unroll
        for (int g = 0; g < 2; g++) {
            const int off = cq * 8 + 4 * g;
            uint4 aA[2], aB[2];
#pragma unroll
            for (int mi = 0; mi < 2; mi++) {
                int rowA = mWarp + mi * 16;
                aA[mi] = *(const uint4*)(Ab + (rowA + r)     * ASTR + off);
                aB[mi] = *(const uint4*)(Ab + (rowA + r + 8) * ASTR + off);
            }
            uint4 bf[4];
#pragma unroll
            for (int ni = 0; ni < 4; ni++)
                bf[ni] = *(const uint4*)(Bb + (nWarp + ni * 8 + r) * BSTR + off);
#pragma unroll
            for (int mi = 0; mi < 2; mi++)
#pragma unroll
                for (int ni = 0; ni < 4; ni++) {
                    mma8(acc[mi][ni], aA[mi].x, aB[mi].x, aA[mi].y, aB[mi].y,
                         bf[ni].x, bf[ni].y);
                    mma8(acc[mi][ni], aA[mi].z, aB[mi].z, aA[mi].w, aB[mi].w,
                         bf[ni].z, bf[ni].w);
                }
        }

        if (hasNext) {
            const int nb = buf ^ 1;
            unsigned* ad = As + nb * BM * ASTR + arow * ASTR + (khalf >> 2);
            const float* fr = (const float*)ra;
#pragma unroll
            for (int e = 0; e < 4; e++) {
                uint4 s;
                s.x = f2tf(fr[e]); s.y = f2tf(fr[4 + e]);
                s.z = f2tf(fr[8 + e]); s.w = f2tf(fr[12 + e]);
                *(uint4*)(ad + e * 8) = s;
            }
            unsigned* bd = Bs + nb * BN * BSTR + bn * BSTR + (bk8 >> 2);
#pragma unroll
            for (int e = 0; e < 4; e++) {
                uint2 s;
                s.x = f2tf(rbv[e]); s.y = f2tf(rbv[e + 4]);
                *(uint2*)(bd + e * 8) = s;
            }
        }
        __syncthreads();
    }

#pragma unroll
    for (int mi = 0; mi < 2; mi++) {
#pragma unroll
        for (int ni = 0; ni < 4; ni++) {
            int row0 = rowBase + mWarp + mi * 16 + r;
            int col  = colBase + nWarp + ni * 8 + 2 * cq;
#pragma unroll
            for (int half = 0; half < 2; half++) {
                int rr = row0 + half * 8;
                float v0 = acc[mi][ni][half * 2 + 0];
                float v1 = acc[mi][ni][half * 2 + 1];
                if (bias) { v0 += bias[col]; v1 += bias[col + 1]; }
                if (res) {
                    float2 rv = *(const float2*)(res + (long)rr * ldc + col);
                    v0 += rv.x; v1 += rv.y;
                }
                if (GELU_ACT) {
                    v0 = 0.5f * v0 * (1.f + erff(v0 * 0.70710678118654752f));
                    v1 = 0.5f * v1 * (1.f + erff(v1 * 0.70710678118654752f));
                }
                float2 ov; ov.x = v0; ov.y = v1;
                *(float2*)(Cm + (long)rr * ldc + col) = ov;
            }
        }
    }
}

// ---- fused flash attention (full attention, no-max softmax) ----
// grid (Tv/QROWS, Bv*Hv), 256 threads.
__global__ __launch_bounds__(256) void attn_k(
    const float* __restrict__ q,
    const float* __restrict__ k,
    const float* __restrict__ v,
    float* __restrict__ y)
{
    extern __shared__ unsigned sm_[];
    unsigned* Qs = sm_;                        // [128][DSTR]
    unsigned* Ks = Qs + QROWS * DSTR;          // [2][64][DSTR]
    unsigned* Vs = Ks + 2 * KTILE * DSTR;      // [2][64][DSTR]
    unsigned* Ps = Vs + 2 * KTILE * DSTR;      // [128][DSTR]

    const int tid  = threadIdx.x;
    const int lane = tid & 31;
    const int wid  = tid >> 5;
    const int r  = lane >> 2;
    const int cq = lane & 3;

    const int bh = blockIdx.y;
    const long base = (long)(bh >> 3) * Tv * Cv + (bh & 7) * DHv;
    const int q0 = blockIdx.x * QROWS;

    // load Q (pre-scaled), two 32-d blocks per row, permuted
    {
        int row = tid & 127;
        int d0  = (tid >> 7) * 32;
        const float* src = q + base + (long)(q0 + row) * Cv + d0;
        float4 f[8];
#pragma unroll
        for (int u = 0; u < 8; u++) f[u] = *(const float4*)(src + 4 * u);
        unsigned* dst = Qs + row * DSTR + d0;
        const float* ff = (const float*)f;
#pragma unroll
        for (int e = 0; e < 4; e++) {
            uint4 s0, s1;
            s0.x = f2tf(ff[e] * SCALE);      s0.y = f2tf(ff[4 + e] * SCALE);
            s0.z = f2tf(ff[8 + e] * SCALE);  s0.w = f2tf(ff[12 + e] * SCALE);
            s1.x = f2tf(ff[16 + e] * SCALE); s1.y = f2tf(ff[20 + e] * SCALE);
            s1.z = f2tf(ff[24 + e] * SCALE); s1.w = f2tf(ff[28 + e] * SCALE);
            *(uint4*)(dst + e * 8)     = s0;
            *(uint4*)(dst + e * 8 + 4) = s1;
        }
    }

    const int krK = tid & 63;
    const int d0K = (tid >> 6) * 16;
    const int dV   = tid & 63;
    const int kr0V = (tid >> 6) * 16;

    float4 kf[4];
    float  vf[16];
    {
        const float* ks = k + base + (long)krK * Cv + d0K;
#pragma unroll
        for (int u = 0; u < 4; u++) kf[u] = *(const float4*)(ks + 4 * u);
        const float* vs = v + base + (long)kr0V * Cv + dV;
#pragma unroll
        for (int j = 0; j < 16; j++) vf[j] = vs[(long)j * Cv];
    }
    {
        unsigned* kd = Ks + krK * DSTR + (d0K & 32) + 4 * ((d0K >> 4) & 1);
        const float* fk = (const float*)kf;
#pragma unroll
        for (int e = 0; e < 4; e++) {
            uint4 s;
            s.x = f2tf(fk[e]); s.y = f2tf(fk[4 + e]);
            s.z = f2tf(fk[8 + e]); s.w = f2tf(fk[12 + e]);
            *(uint4*)(kd + e * 8) = s;
        }
        unsigned* vd = Vs + dV * DSTR + (kr0V & 32) + 4 * ((kr0V >> 4) & 1);
#pragma unroll
        for (int e = 0; e < 4; e++) {
            uint4 s;
            s.x = f2tf(vf[e]); s.y = f2tf(vf[4 + e]);
            s.z = f2tf(vf[8 + e]); s.w = f2tf(vf[12 + e]);
            *(uint4*)(vd + e * 8) = s;
        }
    }
    __syncthreads();

    float o[8][4];
#pragma unroll
    for (int nf = 0; nf < 8; nf++)
#pragma unroll
        for (int t = 0; t < 4; t++) o[nf][t] = 0.f;
    float lp0 = 0.f, lp1 = 0.f;

    const int v0i = 2 * cq, v1i = 2 * cq + 1;
    const int pv0 = (v0i & 3) * 8 + (v0i >> 2);
    const int pv1 = (v1i & 3) * 8 + (v1i >> 2);
    const int qrow0 = wid * 16 + r;

    for (int t = 0; t < 8; t++) {
        const int buf = t & 1;
        const bool hasNext = (t < 7);

        if (hasNext) {
            const float* ks = k + base + (long)((t + 1) * 64 + krK) * Cv + d0K;
#pragma unroll
            for (int u = 0; u < 4; u++) kf[u] = *(const float4*)(ks + 4 * u);
            const float* vs = v + base + (long)((t + 1) * 64 + kr0V) * Cv + dV;
#pragma unroll
            for (int j = 0; j < 16; j++) vf[j] = vs[(long)j * Cv];
        }

        float s[8][4];
#pragma unroll
        for (int nf = 0; nf < 8; nf++)
#pragma unroll
            for (int c = 0; c < 4; c++) s[nf][c] = 0.f;

        const unsigned* Kb = Ks + buf * KTILE * DSTR;
#pragma unroll
        for (int blk = 0; blk < 2; blk++) {
#pragma unroll
            for (int g = 0; g < 2; g++) {
                const int off = blk * 32 + cq * 8 + 4 * g;
                uint4 aA = *(const uint4*)(Qs + (qrow0)     * DSTR + off);
                uint4 aB = *(const uint4*)(Qs + (qrow0 + 8) * DSTR + off);
#pragma unroll
                for (int nf = 0; nf < 8; nf++) {
                    uint4 bb = *(const uint4*)(Kb + (nf * 8 + r) * DSTR + off);
                    mma8(s[nf], aA.x, aB.x, aA.y, aB.y, bb.x, bb.y);
                    mma8(s[nf], aA.z, aB.z, aA.w, aB.w, bb.z, bb.w);
                }
            }
        }

#pragma unroll
        for (int nf = 0; nf < 8; nf++) {
            float e0 = __expf(s[nf][0]);
            float e1 = __expf(s[nf][1]);
            float e2 = __expf(s[nf][2]);
            float e3 = __expf(s[nf][3]);
            lp0 += e0 + e1;
            lp1 += e2 + e3;
            unsigned* pr0 = Ps + (qrow0)     * DSTR + (nf >> 2) * 32 + 2 * (nf & 3);
            unsigned* pr1 = Ps + (qrow0 + 8) * DSTR + (nf >> 2) * 32 + 2 * (nf & 3);
            pr0[pv0] = f2tf(e0); pr0[pv1] = f2tf(e1);
            pr1[pv0] = f2tf(e2); pr1[pv1] = f2tf(e3);
        }
        __syncwarp();   // P rows are warp-private

        const unsigned* Vb = Vs + buf * KTILE * DSTR;
#pragma unroll
        for (int blk = 0; blk < 2; blk++) {
#pragma unroll
            for (int g = 0; g < 2; g++) {
                const int off = blk * 32 + cq * 8 + 4 * g;
                uint4 aA = *(const uint4*)(Ps + (qrow0)     * DSTR + off);
                uint4 aB = *(const uint4*)(Ps + (qrow0 + 8) * DSTR + off);
#pragma unroll
                for (int nf = 0; nf < 8; nf++) {
                    uint4 bb = *(const uint4*)(Vb + (nf * 8 + r) * DSTR + off);
                    mma8(o[nf], aA.x, aB.x, aA.y, aB.y, bb.x, bb.y);
                    mma8(o[nf], aA.z, aB.z, aA.w, aB.w, bb.z, bb.w);
                }
            }
        }

        if (hasNext) {
            const int nb = buf ^ 1;
            unsigned* kd = Ks + nb * KTILE * DSTR + krK * DSTR + (d0K & 32) + 4 * ((d0K >> 4) & 1);
            const float* fk = (const float*)kf;
#pragma unroll
            for (int e = 0; e < 4; e++) {
                uint4 ss;
                ss.x = f2tf(fk[e]); ss.y = f2tf(fk[4 + e]);
                ss.z = f2tf(fk[8 + e]); ss.w = f2tf(fk[12 + e]);
                *(uint4*)(kd + e * 8) = ss;
            }
            unsigned* vd = Vs + nb * KTILE * DSTR + dV * DSTR + (kr0V & 32) + 4 * ((kr0V >> 4) & 1);
#pragma unroll
            for (int e = 0; e < 4; e++) {
                uint4 ss;
                ss.x = f2tf(vf[e]); ss.y = f2tf(vf[4 + e]);
                ss.z = f2tf(vf[8 + e]); ss.w = f2tf(vf[12 + e]);
                *(uint4*)(vd + e * 8) = ss;
            }
        }
        __syncthreads();
    }

    lp0 += __shfl_xor_sync(0xffffffffu, lp0, 1);
    lp0 += __shfl_xor_sync(0xffffffffu, lp0, 2);
    lp1 += __shfl_xor_sync(0xffffffffu, lp1, 1);
    lp1 += __shfl_xor_sync(0xffffffffu, lp1, 2);
    const float i0 = 1.f / lp0;
    const float i1 = 1.f / lp1;

    const long outRow0 = (long)(bh >> 3) * Tv + q0 + qrow0;
    const int  colB = (bh & 7) * DHv;
#pragma unroll
    for (int nf = 0; nf < 8; nf++) {
        int col = colB + nf * 8 + 2 * cq;
        float2 w0; w0.x = o[nf][0] * i0; w0.y = o[nf][1] * i0;
        float2 w1; w1.x = o[nf][2] * i1; w1.y = o[nf][3] * i1;
        *(float2*)(y + (outRow0)     * Cv + col) = w0;
        *(float2*)(y + (outRow0 + 8) * Cv + col) = w1;
    }
}

extern "C" void kernel_launch(void* const* d_in, const int* in_sizes, int n_in,
                              void* d_out, int out_size)
{
    const int*   idx   = (const int*)  d_in[0];
    const float* tok   = (const float*)d_in[1];
    const float* pos   = (const float*)d_in[2];
    const float* ln1g  = (const float*)d_in[3];
    const float* ln1b  = (const float*)d_in[4];
    const float* Wq    = (const float*)d_in[5];
    const float* bq    = (const float*)d_in[6];
    const float* Wk    = (const float*)d_in[7];
    const float* bk    = (const float*)d_in[8];
    const float* Wv    = (const float*)d_in[9];
    const float* bv    = (const float*)d_in[10];
    const float* Wp    = (const float*)d_in[11];
    const float* bp    = (const float*)d_in[12];
    const float* ln2g  = (const float*)d_in[13];
    const float* ln2b  = (const float*)d_in[14];
    const float* W1    = (const float*)d_in[15];
    const float* b1    = (const float*)d_in[16];
    const float* W2    = (const float*)d_in[17];
    const float* b2    = (const float*)d_in[18];
    const float* lnfg  = (const float*)d_in[19];
    const float* lnfb  = (const float*)d_in[20];
    const float* Whead = (const float*)d_in[21];
    float* out = (float*)d_out;

    float *x, *xn, *q, *k, *v, *y, *h;
    cudaGetSymbolAddress((void**)&x,  g_x);
    cudaGetSymbolAddress((void**)&xn, g_xn);
    cudaGetSymbolAddress((void**)&q,  g_q);
    cudaGetSymbolAddress((void**)&k,  g_k);
    cudaGetSymbolAddress((void**)&v,  g_v);
    cudaGetSymbolAddress((void**)&y,  g_y);
    cudaGetSymbolAddress((void**)&h,  g_h);

    cudaFuncSetAttribute(gemm_tc<false>,
                         cudaFuncAttributeMaxDynamicSharedMemorySize, SMEM_BYTES);
    cudaFuncSetAttribute(gemm_tc<true>,
                         cudaFuncAttributeMaxDynamicSharedMemorySize, SMEM_BYTES);
    cudaFuncSetAttribute(attn_k,
                         cudaFuncAttributeMaxDynamicSharedMemorySize, ATT_SMEM_BYTES);

    embed_k<<<(MALL * Cv) / 256, 256>>>(idx, tok, pos, x);

    for (int s = 0; s < STEPS; s++) {
        for (int l = 0; l < Lv; l++) {
            const float* wq = Wq + (long)l * Cv * Cv;
            const float* wk = Wk + (long)l * Cv * Cv;
            const float* wv = Wv + (long)l * Cv * Cv;
            const float* wp = Wp + (long)l * Cv * Cv;
            const float* w1 = W1 + (long)l * Cv * FFv;
            const float* w2 = W2 + (long)l * FFv * Cv;

            ln_k<<<MALL, 256>>>(x, ln1g + l * Cv, ln1b + l * Cv, xn);

            dim3 gProj(Cv / BN, MALL / BM, 1);
            gemm_tc<false><<<gProj, 256, SMEM_BYTES>>>(
                xn, Cv, wq, Cv, bq + l * Cv, nullptr, q, Cv, Cv);
            gemm_tc<false><<<gProj, 256, SMEM_BYTES>>>(
                xn, Cv, wk, Cv, bk + l * Cv, nullptr, k, Cv, Cv);
            gemm_tc<false><<<gProj, 256, SMEM_BYTES>>>(
                xn, Cv, wv, Cv, bv + l * Cv, nullptr, v, Cv, Cv);

            dim3 gAtt(Tv / QROWS, Bv * Hv, 1);
            attn_k<<<gAtt, 256, ATT_SMEM_BYTES>>>(q, k, v, y);

            gemm_tc<false><<<gProj, 256, SMEM_BYTES>>>(
                y, Cv, wp, Cv, bp + l * Cv, x, x, Cv, Cv);

            ln_k<<<MALL, 256>>>(x, ln2g + l * Cv, ln2b + l * Cv, xn);

            dim3 gFF1(FFv / BN, MALL / BM, 1);
            gemm_tc<true><<<gFF1, 256, SMEM_BYTES>>>(
                xn, Cv, w1, FFv, b1 + l * FFv, nullptr, h, FFv, Cv);

            gemm_tc<false><<<gProj, 256, SMEM_BYTES>>>(
                h, FFv, w2, Cv, b2 + l * Cv, x, x, Cv, FFv);
        }
    }

    ln_k<<<MALL, 256>>>(x, lnfg, lnfb, xn);
    dim3 gHead(Vv / BN, MALL / BM, 1);
    gemm_tc<false><<<gHead, 256, SMEM_BYTES>>>(
        xn, Cv, Whead, Vv, nullptr, nullptr, out, Vv, Cv);
}

// round 5
// speedup vs baseline: 1.3594x; 1.3594x over previous
#include <cuda_runtime.h>
#include <math.h>

#define Bv    8
#define Tv    512
#define Cv    512
#define Hv    8
#define DHv   64
#define Lv    2
#define Vv    512
#define FFv   2048
#define STEPS 4
#define MALL  (Bv*Tv)
#define SCALE 0.125f
#define QKVW  1536

#define BM 128
#define BN 64
#define BK 32
#define ASTR (BK + 4)
#define BSTR (BN + 8)
#define SMEM_BYTES ((2*BM*ASTR + 2*BK*BSTR) * 4)

#define QROWS 128
#define KTILE 64
#define DSTR  68
#define ATT_SMEM_BYTES ((2*QROWS*DSTR + 4*KTILE*DSTR)*4)

__device__ float g_x  [MALL*Cv];
__device__ float g_xn [MALL*Cv];
__device__ float g_qkv[MALL*QKVW];
__device__ float g_y  [MALL*Cv];
__device__ float g_h  [MALL*FFv];
__device__ float g_wqkv[Lv*Cv*QKVW];
__device__ float g_bqkv[Lv*QKVW];

__device__ __forceinline__ unsigned f2tf(float f)
{
    unsigned u;
    asm("cvt.rna.tf32.f32 %0, %1;" : "=r"(u) : "f"(f));
    return u;
}

__device__ __forceinline__ void mma8(float acc[4],
                                     unsigned a0, unsigned a1, unsigned a2, unsigned a3,
                                     unsigned b0, unsigned b1)
{
    asm volatile(
        "mma.sync.aligned.m16n8k8.row.col.f32.tf32.tf32.f32 "
        "{%0,%1,%2,%3}, {%4,%5,%6,%7}, {%8,%9}, {%0,%1,%2,%3};\n"
        : "+f"(acc[0]), "+f"(acc[1]), "+f"(acc[2]), "+f"(acc[3])
        : "r"(a0), "r"(a1), "r"(a2), "r"(a3), "r"(b0), "r"(b1));
}

__global__ void embed_k(const int* __restrict__ idx,
                        const float* __restrict__ tok,
                        const float* __restrict__ pos,
                        float* __restrict__ x)
{
    int i = blockIdx.x * 256 + threadIdx.x;
    int c  = i & (Cv - 1);
    int bt = i >> 9;
    int t  = bt & (Tv - 1);
    x[i] = tok[idx[bt] * Cv + c] + pos[t * Cv + c];
}

__global__ void pack_w_k(const float* __restrict__ Wq,
                         const float* __restrict__ Wk,
                         const float* __restrict__ Wv,
                         float* __restrict__ out)
{
    int i = blockIdx.x * 256 + threadIdx.x;       // Lv*Cv*QKVW
    int j = i % QKVW;
    int rem = i / QKVW;
    int kk = rem % Cv;
    int l  = rem / Cv;
    int sel = j >> 9, col = j & 511;
    const float* W = (sel == 0) ? Wq : (sel == 1) ? Wk : Wv;
    out[i] = W[((long)l * Cv + kk) * Cv + col];
}

__global__ void pack_b_k(const float* __restrict__ bq,
                         const float* __restrict__ bk,
                         const float* __restrict__ bv,
                         float* __restrict__ out)
{
    int i = blockIdx.x * 256 + threadIdx.x;       // Lv*QKVW
    int j = i % QKVW;
    int l = i / QKVW;
    int sel = j >> 9, col = j & 511;
    const float* bb = (sel == 0) ? bq : (sel == 1) ? bk : bv;
    out[i] = bb[l * Cv + col];
}

__device__ __forceinline__ float block_sum(float v, float* red)
{
    for (int o = 16; o > 0; o >>= 1) v += __shfl_xor_sync(0xffffffffu, v, o);
    int warp = threadIdx.x >> 5, lane = threadIdx.x & 31;
    if (lane == 0) red[warp] = v;
    __syncthreads();
    if (warp == 0) {
        float s = (lane < 8) ? red[lane] : 0.f;
        for (int o = 4; o > 0; o >>= 1) s += __shfl_xor_sync(0xffffffffu, s, o);
        if (lane == 0) red[0] = s;
    }
    __syncthreads();
    float r = red[0];
    __syncthreads();
    return r;
}

__global__ __launch_bounds__(256) void ln_k(const float* __restrict__ x,
                                            const float* __restrict__ g,
                                            const float* __restrict__ b,
                                            float* __restrict__ o)
{
    __shared__ float red[32];
    long row = blockIdx.x;
    const float* xr = x + row * Cv;
    int c0 = threadIdx.x, c1 = threadIdx.x + 256;
    float v0 = xr[c0], v1 = xr[c1];
    float mu = block_sum(v0 + v1, red) * (1.f / Cv);
    float d0 = v0 - mu, d1 = v1 - mu;
    float var = block_sum(d0 * d0 + d1 * d1, red) * (1.f / Cv);
    float inv = rsqrtf(var + 1e-5f);
    float* orow = o + row * Cv;
    orow[c0] = d0 * inv * g[c0] + b[c0];
    orow[c1] = d1 * inv * g[c1] + b[c1];
}

// ---- tf32 GEMM (round-2 proven version) ----
template <bool GELU_ACT>
__global__ __launch_bounds__(256) void gemm_tc(
    const float* __restrict__ A, int lda,
    const float* __restrict__ Bm, int ldb,
    const float* __restrict__ bias,
    const float* __restrict__ res,
    float* __restrict__ Cm, int ldc,
    int K)
{
    extern __shared__ unsigned sm_[];
    unsigned* As = sm_;                         // [2][BM][ASTR]
    unsigned* Bs = sm_ + 2 * BM * ASTR;         // [2][BK][BSTR]
#define AS(b,m,k) As[(((b)*BM) + (m))*ASTR + (k)]
#define BS(b,k,n) Bs[(((b)*BK) + (k))*BSTR + (n)]

    const int tid  = threadIdx.x;
    const int lane = tid & 31;
    const int wid  = tid >> 5;
    const int mWarp = (wid >> 1) * 32;
    const int nWarp = (wid & 1) * 32;
    const int rowBase = blockIdx.y * BM;
    const int colBase = blockIdx.x * BN;

    const int r  = lane >> 2;
    const int cq = lane & 3;

    float acc[2][4][4];
#pragma unroll
    for (int mi = 0; mi < 2; mi++)
#pragma unroll
        for (int ni = 0; ni < 4; ni++)
#pragma unroll
            for (int t = 0; t < 4; t++) acc[mi][ni][t] = 0.f;

    const int KT = K / BK;
    float4 ra[4];
    float4 rb[2];

    {
#pragma unroll
        for (int i = 0; i < 4; i++) {
            int f = tid + i * 256;
            int row = f >> 3, c4 = (f & 7) * 4;
            ra[i] = *(const float4*)(A + (long)(rowBase + row) * lda + c4);
        }
#pragma unroll
        for (int i = 0; i < 2; i++) {
            int f = tid + i * 256;
            int kk = f >> 4, n4 = (f & 15) * 4;
            rb[i] = *(const float4*)(Bm + (long)kk * ldb + colBase + n4);
        }
#pragma unroll
        for (int i = 0; i < 4; i++) {
            int f = tid + i * 256;
            int row = f >> 3, c4 = (f & 7) * 4;
            AS(0, row, c4 + 0) = f2tf(ra[i].x);
            AS(0, row, c4 + 1) = f2tf(ra[i].y);
            AS(0, row, c4 + 2) = f2tf(ra[i].z);
            AS(0, row, c4 + 3) = f2tf(ra[i].w);
        }
#pragma unroll
        for (int i = 0; i < 2; i++) {
            int f = tid + i * 256;
            int kk = f >> 4, n4 = (f & 15) * 4;
            BS(0, kk, n4 + 0) = f2tf(rb[i].x);
            BS(0, kk, n4 + 1) = f2tf(rb[i].y);
            BS(0, kk, n4 + 2) = f2tf(rb[i].z);
            BS(0, kk, n4 + 3) = f2tf(rb[i].w);
        }
    }
    __syncthreads();

    for (int kt = 0; kt < KT; kt++) {
        const int buf = kt & 1;
        const bool hasNext = (kt + 1 < KT);

        if (hasNext) {
            const int k0 = (kt + 1) * BK;
#pragma unroll
            for (int i = 0; i < 4; i++) {
                int f = tid + i * 256;
                int row = f >> 3, c4 = (f & 7) * 4;
                ra[i] = *(const float4*)(A + (long)(rowBase + row) * lda + k0 + c4);
            }
#pragma unroll
            for (int i = 0; i < 2; i++) {
                int f = tid + i * 256;
                int kk = f >> 4, n4 = (f & 15) * 4;
                rb[i] = *(const float4*)(Bm + (long)(k0 + kk) * ldb + colBase + n4);
            }
        }

#pragma unroll
        for (int ks = 0; ks < 4; ks++) {
            const int kb = ks * 8;
            unsigned a[2][4];
#pragma unroll
            for (int mi = 0; mi < 2; mi++) {
                int m = mWarp + mi * 16;
                a[mi][0] = AS(buf, m + r,     kb + cq);
                a[mi][1] = AS(buf, m + r + 8, kb + cq);
                a[mi][2] = AS(buf, m + r,     kb + cq + 4);
                a[mi][3] = AS(buf, m + r + 8, kb + cq + 4);
            }
            unsigned bb[4][2];
#pragma unroll
            for (int ni = 0; ni < 4; ni++) {
                int n = nWarp + ni * 8 + r;
                bb[ni][0] = BS(buf, kb + cq,     n);
                bb[ni][1] = BS(buf, kb + cq + 4, n);
            }
#pragma unroll
            for (int mi = 0; mi < 2; mi++)
#pragma unroll
                for (int ni = 0; ni < 4; ni++)
                    mma8(acc[mi][ni], a[mi][0], a[mi][1], a[mi][2], a[mi][3],
                         bb[ni][0], bb[ni][1]);
        }

        if (hasNext) {
            const int nb = buf ^ 1;
#pragma unroll
            for (int i = 0; i < 4; i++) {
                int f = tid + i * 256;
                int row = f >> 3, c4 = (f & 7) * 4;
                AS(nb, row, c4 + 0) = f2tf(ra[i].x);
                AS(nb, row, c4 + 1) = f2tf(ra[i].y);
                AS(nb, row, c4 + 2) = f2tf(ra[i].z);
                AS(nb, row, c4 + 3) = f2tf(ra[i].w);
            }
#pragma unroll
            for (int i = 0; i < 2; i++) {
                int f = tid + i * 256;
                int kk = f >> 4, n4 = (f & 15) * 4;
                BS(nb, kk, n4 + 0) = f2tf(rb[i].x);
                BS(nb, kk, n4 + 1) = f2tf(rb[i].y);
                BS(nb, kk, n4 + 2) = f2tf(rb[i].z);
                BS(nb, kk, n4 + 3) = f2tf(rb[i].w);
            }
        }
        __syncthreads();
    }

#pragma unroll
    for (int mi = 0; mi < 2; mi++) {
#pragma unroll
        for (int ni = 0; ni < 4; ni++) {
            int row0 = rowBase + mWarp + mi * 16 + r;
            int col  = colBase + nWarp + ni * 8 + 2 * cq;
#pragma unroll
            for (int half = 0; half < 2; half++) {
                int rr = row0 + half * 8;
                float v0 = acc[mi][ni][half * 2 + 0];
                float v1 = acc[mi][ni][half * 2 + 1];
                if (bias) { v0 += bias[col]; v1 += bias[col + 1]; }
                if (res) {
                    float2 rv = *(const float2*)(res + (long)rr * ldc + col);
                    v0 += rv.x; v1 += rv.y;
                }
                if (GELU_ACT) {
                    v0 = 0.5f * v0 * (1.f + erff(v0 * 0.70710678118654752f));
                    v1 = 0.5f * v1 * (1.f + erff(v1 * 0.70710678118654752f));
                }
                float2 ov; ov.x = v0; ov.y = v1;
                *(float2*)(Cm + (long)rr * ldc + col) = ov;
            }
        }
    }
#undef AS
#undef BS
}

// ---- fused flash attention over packed QKV (ld = QKVW) ----
__global__ __launch_bounds__(256) void attn_k(
    const float* __restrict__ qkv,
    float* __restrict__ y)
{
    extern __shared__ unsigned sm_[];
    unsigned* Qs = sm_;
    unsigned* Ks = Qs + QROWS * DSTR;
    unsigned* Vs = Ks + 2 * KTILE * DSTR;
    unsigned* Ps = Vs + 2 * KTILE * DSTR;

    const int tid  = threadIdx.x;
    const int lane = tid & 31;
    const int wid  = tid >> 5;
    const int r  = lane >> 2;
    const int cq = lane & 3;

    const int bh = blockIdx.y;
    const long base = (long)(bh >> 3) * Tv * QKVW + (bh & 7) * DHv;
    const float* q = qkv + base;
    const float* k = qkv + base + Cv;
    const float* v = qkv + base + 2 * Cv;
    const int q0 = blockIdx.x * QROWS;

    {
        int row = tid & 127;
        int d0  = (tid >> 7) * 32;
        const float* src = q + (long)(q0 + row) * QKVW + d0;
        float4 f[8];
#pragma unroll
        for (int u = 0; u < 8; u++) f[u] = *(const float4*)(src + 4 * u);
        unsigned* dst = Qs + row * DSTR + d0;
        const float* ff = (const float*)f;
#pragma unroll
        for (int e = 0; e < 4; e++) {
            uint4 s0, s1;
            s0.x = f2tf(ff[e] * SCALE);      s0.y = f2tf(ff[4 + e] * SCALE);
            s0.z = f2tf(ff[8 + e] * SCALE);  s0.w = f2tf(ff[12 + e] * SCALE);
            s1.x = f2tf(ff[16 + e] * SCALE); s1.y = f2tf(ff[20 + e] * SCALE);
            s1.z = f2tf(ff[24 + e] * SCALE); s1.w = f2tf(ff[28 + e] * SCALE);
            *(uint4*)(dst + e * 8)     = s0;
            *(uint4*)(dst + e * 8 + 4) = s1;
        }
    }

    const int krK = tid & 63;
    const int d0K = (tid >> 6) * 16;
    const int dV   = tid & 63;
    const int kr0V = (tid >> 6) * 16;

    float4 kf[4];
    float  vf[16];
    {
        const float* ks = k + (long)krK * QKVW + d0K;
#pragma unroll
        for (int u = 0; u < 4; u++) kf[u] = *(const float4*)(ks + 4 * u);
        const float* vs = v + (long)kr0V * QKVW + dV;
#pragma unroll
        for (int j = 0; j < 16; j++) vf[j] = vs[(long)j * QKVW];
    }
    {
        unsigned* kd = Ks + krK * DSTR + (d0K & 32) + 4 * ((d0K >> 4) & 1);
        const float* fk = (const float*)kf;
#pragma unroll
        for (int e = 0; e < 4; e++) {
            uint4 s;
            s.x = f2tf(fk[e]); s.y = f2tf(fk[4 + e]);
            s.z = f2tf(fk[8 + e]); s.w = f2tf(fk[12 + e]);
            *(uint4*)(kd + e * 8) = s;
        }
        unsigned* vd = Vs + dV * DSTR + (kr0V & 32) + 4 * ((kr0V >> 4) & 1);
#pragma unroll
        for (int e = 0; e < 4; e++) {
            uint4 s;
            s.x = f2tf(vf[e]); s.y = f2tf(vf[4 + e]);
            s.z = f2tf(vf[8 + e]); s.w = f2tf(vf[12 + e]);
            *(uint4*)(vd + e * 8) = s;
        }
    }
    __syncthreads();

    float o[8][4];
#pragma unroll
    for (int nf = 0; nf < 8; nf++)
#pragma unroll
        for (int t = 0; t < 4; t++) o[nf][t] = 0.f;
    float lp0 = 0.f, lp1 = 0.f;

    const int v0i = 2 * cq, v1i = 2 * cq + 1;
    const int pv0 = (v0i & 3) * 8 + (v0i >> 2);
    const int pv1 = (v1i & 3) * 8 + (v1i >> 2);
    const int qrow0 = wid * 16 + r;

    for (int t = 0; t < 8; t++) {
        const int buf = t & 1;
        const bool hasNext = (t < 7);

        if (hasNext) {
            const float* ks = k + (long)((t + 1) * 64 + krK) * QKVW + d0K;
#pragma unroll
            for (int u = 0; u < 4; u++) kf[u] = *(const float4*)(ks + 4 * u);
            const float* vs = v + (long)((t + 1) * 64 + kr0V) * QKVW + dV;
#pragma unroll
            for (int j = 0; j < 16; j++) vf[j] = vs[(long)j * QKVW];
        }

        float s[8][4];
#pragma unroll
        for (int nf = 0; nf < 8; nf++)
#pragma unroll
            for (int c = 0; c < 4; c++) s[nf][c] = 0.f;

        const unsigned* Kb = Ks + buf * KTILE * DSTR;
#pragma unroll
        for (int blk = 0; blk < 2; blk++) {
#pragma unroll
            for (int g = 0; g < 2; g++) {
                const int off = blk * 32 + cq * 8 + 4 * g;
                uint4 aA = *(const uint4*)(Qs + (qrow0)     * DSTR + off);
                uint4 aB = *(const uint4*)(Qs + (qrow0 + 8) * DSTR + off);
#pragma unroll
                for (int nf = 0; nf < 8; nf++) {
                    uint4 bb = *(const uint4*)(Kb + (nf * 8 + r) * DSTR + off);
                    mma8(s[nf], aA.x, aB.x, aA.y, aB.y, bb.x, bb.y);
                    mma8(s[nf], aA.z, aB.z, aA.w, aB.w, bb.z, bb.w);
                }
            }
        }

#pragma unroll
        for (int nf = 0; nf < 8; nf++) {
            float e0 = __expf(s[nf][0]);
            float e1 = __expf(s[nf][1]);
            float e2 = __expf(s[nf][2]);
            float e3 = __expf(s[nf][3]);
            lp0 += e0 + e1;
            lp1 += e2 + e3;
            unsigned* pr0 = Ps + (qrow0)     * DSTR + (nf >> 2) * 32 + 2 * (nf & 3);
            unsigned* pr1 = Ps + (qrow0 + 8) * DSTR + (nf >> 2) * 32 + 2 * (nf & 3);
            pr0[pv0] = f2tf(e0); pr0[pv1] = f2tf(e1);
            pr1[pv0] = f2tf(e2); pr1[pv1] = f2tf(e3);
        }
        __syncwarp();

        const unsigned* Vb = Vs + buf * KTILE * DSTR;
#pragma unroll
        for (int blk = 0; blk < 2; blk++) {
#pragma unroll
            for (int g = 0; g < 2; g++) {
                const int off = blk * 32 + cq * 8 + 4 * g;
                uint4 aA = *(const uint4*)(Ps + (qrow0)     * DSTR + off);
                uint4 aB = *(const uint4*)(Ps + (qrow0 + 8) * DSTR + off);
#pragma unroll
                for (int nf = 0; nf < 8; nf++) {
                    uint4 bb = *(const uint4*)(Vb + (nf * 8 + r) * DSTR + off);
                    mma8(o[nf], aA.x, aB.x, aA.y, aB.y, bb.x, bb.y);
                    mma8(o[nf], aA.z, aB.z, aA.w, aB.w, bb.z, bb.w);
                }
            }
        }

        if (hasNext) {
            const int nb = buf ^ 1;
            unsigned* kd = Ks + nb * KTILE * DSTR + krK * DSTR + (d0K & 32) + 4 * ((d0K >> 4) & 1);
            const float* fk = (const float*)kf;
#pragma unroll
            for (int e = 0; e < 4; e++) {
                uint4 ss;
                ss.x = f2tf(fk[e]); ss.y = f2tf(fk[4 + e]);
                ss.z = f2tf(fk[8 + e]); ss.w = f2tf(fk[12 + e]);
                *(uint4*)(kd + e * 8) = ss;
            }
            unsigned* vd = Vs + nb * KTILE * DSTR + dV * DSTR + (kr0V & 32) + 4 * ((kr0V >> 4) & 1);
#pragma unroll
            for (int e = 0; e < 4; e++) {
                uint4 ss;
                ss.x = f2tf(vf[e]); ss.y = f2tf(vf[4 + e]);
                ss.z = f2tf(vf[8 + e]); ss.w = f2tf(vf[12 + e]);
                *(uint4*)(vd + e * 8) = ss;
            }
        }
        __syncthreads();
    }

    lp0 += __shfl_xor_sync(0xffffffffu, lp0, 1);
    lp0 += __shfl_xor_sync(0xffffffffu, lp0, 2);
    lp1 += __shfl_xor_sync(0xffffffffu, lp1, 1);
    lp1 += __shfl_xor_sync(0xffffffffu, lp1, 2);
    const float i0 = 1.f / lp0;
    const float i1 = 1.f / lp1;

    const long outRow0 = (long)(bh >> 3) * Tv + q0 + qrow0;
    const int  colB = (bh & 7) * DHv;
#pragma unroll
    for (int nf = 0; nf < 8; nf++) {
        int col = colB + nf * 8 + 2 * cq;
        float2 w0; w0.x = o[nf][0] * i0; w0.y = o[nf][1] * i0;
        float2 w1; w1.x = o[nf][2] * i1; w1.y = o[nf][3] * i1;
        *(float2*)(y + (outRow0)     * Cv + col) = w0;
        *(float2*)(y + (outRow0 + 8) * Cv + col) = w1;
    }
}

extern "C" void kernel_launch(void* const* d_in, const int* in_sizes, int n_in,
                              void* d_out, int out_size)
{
    const int*   idx   = (const int*)  d_in[0];
    const float* tok   = (const float*)d_in[1];
    const float* pos   = (const float*)d_in[2];
    const float* ln1g  = (const float*)d_in[3];
    const float* ln1b  = (const float*)d_in[4];
    const float* Wq    = (const float*)d_in[5];
    const float* bq    = (const float*)d_in[6];
    const float* Wk    = (const float*)d_in[7];
    const float* bk    = (const float*)d_in[8];
    const float* Wv    = (const float*)d_in[9];
    const float* bv    = (const float*)d_in[10];
    const float* Wp    = (const float*)d_in[11];
    const float* bp    = (const float*)d_in[12];
    const float* ln2g  = (const float*)d_in[13];
    const float* ln2b  = (const float*)d_in[14];
    const float* W1    = (const float*)d_in[15];
    const float* b1    = (const float*)d_in[16];
    const float* W2    = (const float*)d_in[17];
    const float* b2    = (const float*)d_in[18];
    const float* lnfg  = (const float*)d_in[19];
    const float* lnfb  = (const float*)d_in[20];
    const float* Whead = (const float*)d_in[21];
    float* out = (float*)d_out;

    float *x, *xn, *qkv, *y, *h, *wqkv, *bqkv;
    cudaGetSymbolAddress((void**)&x,    g_x);
    cudaGetSymbolAddress((void**)&xn,   g_xn);
    cudaGetSymbolAddress((void**)&qkv,  g_qkv);
    cudaGetSymbolAddress((void**)&y,    g_y);
    cudaGetSymbolAddress((void**)&h,    g_h);
    cudaGetSymbolAddress((void**)&wqkv, g_wqkv);
    cudaGetSymbolAddress((void**)&bqkv, g_bqkv);

    cudaFuncSetAttribute(gemm_tc<false>,
                         cudaFuncAttributeMaxDynamicSharedMemorySize, SMEM_BYTES);
    cudaFuncSetAttribute(gemm_tc<true>,
                         cudaFuncAttributeMaxDynamicSharedMemorySize, SMEM_BYTES);
    cudaFuncSetAttribute(attn_k,
                         cudaFuncAttributeMaxDynamicSharedMemorySize, ATT_SMEM_BYTES);

    pack_w_k<<<(Lv * Cv * QKVW) / 256, 256>>>(Wq, Wk, Wv, wqkv);
    pack_b_k<<<(Lv * QKVW) / 256, 256>>>(bq, bk, bv, bqkv);
    embed_k<<<(MALL * Cv) / 256, 256>>>(idx, tok, pos, x);

    for (int s = 0; s < STEPS; s++) {
        for (int l = 0; l < Lv; l++) {
            const float* wqkv_l = wqkv + (long)l * Cv * QKVW;
            const float* bqkv_l = bqkv + (long)l * QKVW;
            const float* wp = Wp + (long)l * Cv * Cv;
            const float* w1 = W1 + (long)l * Cv * FFv;
            const float* w2 = W2 + (long)l * FFv * Cv;

            ln_k<<<MALL, 256>>>(x, ln1g + l * Cv, ln1b + l * Cv, xn);

            dim3 gQKV(QKVW / BN, MALL / BM, 1);
            gemm_tc<false><<<gQKV, 256, SMEM_BYTES>>>(
                xn, Cv, wqkv_l, QKVW, bqkv_l, nullptr, qkv, QKVW, Cv);

            dim3 gAtt(Tv / QROWS, Bv * Hv, 1);
            attn_k<<<gAtt, 256, ATT_SMEM_BYTES>>>(qkv, y);

            dim3 gProj(Cv / BN, MALL / BM, 1);
            gemm_tc<false><<<gProj, 256, SMEM_BYTES>>>(
                y, Cv, wp, Cv, bp + l * Cv, x, x, Cv, Cv);

            ln_k<<<MALL, 256>>>(x, ln2g + l * Cv, ln2b + l * Cv, xn);

            dim3 gFF1(FFv / BN, MALL / BM, 1);
            gemm_tc<true><<<gFF1, 256, SMEM_BYTES>>>(
                xn, Cv, w1, FFv, b1 + l * FFv, nullptr, h, FFv, Cv);

            gemm_tc<false><<<gProj, 256, SMEM_BYTES>>>(
                h, FFv, w2, Cv, b2 + l * Cv, x, x, Cv, FFv);
        }
    }

    ln_k<<<MALL, 256>>>(x, lnfg, lnfb, xn);
    dim3 gHead(Vv / BN, MALL / BM, 1);
    gemm_tc<false><<<gHead, 256, SMEM_BYTES>>>(
        xn, Cv, Whead, Vv, nullptr, nullptr, out, Vv, Cv);
}

// round 7
// speedup vs baseline: 1.4405x; 1.0597x over previous
#include <cuda_runtime.h>
#include <math.h>

#define Bv    8
#define Tv    512
#define Cv    512
#define Hv    8
#define DHv   64
#define Lv    2
#define Vv    512
#define FFv   2048
#define STEPS 4
#define MALL  (Bv*Tv)
#define SCALE 0.125f
#define QKVW  1536

#define BM 128
#define BN 64
#define BK 32
#define ASTR (BK + 4)
#define BSTR (BN + 8)
#define SMEM_BYTES ((2*BM*ASTR + 2*BK*BSTR) * 4)

#define BN2 128
#define BSTR2 (BN2 + 8)
#define SMEM2_BYTES ((2*BM*ASTR + 2*BK*BSTR2) * 4)   // 71680

#define QROWS 128
#define KTILE 64
#define DSTR  68
#define ATT_SMEM_BYTES ((2*QROWS*DSTR + 4*KTILE*DSTR)*4)

__device__ float g_x  [MALL*Cv];
__device__ float g_xn [MALL*Cv];
__device__ float g_qkv[MALL*QKVW];
__device__ float g_y  [MALL*Cv];
__device__ float g_h  [MALL*FFv];
__device__ float g_wqkv[Lv*Cv*QKVW];
__device__ float g_bqkv[Lv*QKVW];

__device__ __forceinline__ unsigned f2tf(float f)
{
    unsigned u;
    asm("cvt.rna.tf32.f32 %0, %1;" : "=r"(u) : "f"(f));
    return u;
}

__device__ __forceinline__ void mma8(float acc[4],
                                     unsigned a0, unsigned a1, unsigned a2, unsigned a3,
                                     unsigned b0, unsigned b1)
{
    asm volatile(
        "mma.sync.aligned.m16n8k8.row.col.f32.tf32.tf32.f32 "
        "{%0,%1,%2,%3}, {%4,%5,%6,%7}, {%8,%9}, {%0,%1,%2,%3};\n"
        : "+f"(acc[0]), "+f"(acc[1]), "+f"(acc[2]), "+f"(acc[3])
        : "r"(a0), "r"(a1), "r"(a2), "r"(a3), "r"(b0), "r"(b1));
}

__global__ void embed_k(const int* __restrict__ idx,
                        const float* __restrict__ tok,
                        const float* __restrict__ pos,
                        float* __restrict__ x)
{
    int i = blockIdx.x * 256 + threadIdx.x;
    int c  = i & (Cv - 1);
    int bt = i >> 9;
    int t  = bt & (Tv - 1);
    x[i] = tok[idx[bt] * Cv + c] + pos[t * Cv + c];
}

__global__ void pack_w_k(const float* __restrict__ Wq,
                         const float* __restrict__ Wk,
                         const float* __restrict__ Wv,
                         float* __restrict__ out)
{
    int i = blockIdx.x * 256 + threadIdx.x;
    int j = i % QKVW;
    int rem = i / QKVW;
    int kk = rem % Cv;
    int l  = rem / Cv;
    int sel = j >> 9, col = j & 511;
    const float* W = (sel == 0) ? Wq : (sel == 1) ? Wk : Wv;
    out[i] = W[((long)l * Cv + kk) * Cv + col];
}

__global__ void pack_b_k(const float* __restrict__ bq,
                         const float* __restrict__ bk,
                         const float* __restrict__ bv,
                         float* __restrict__ out)
{
    int i = blockIdx.x * 256 + threadIdx.x;
    int j = i % QKVW;
    int l = i / QKVW;
    int sel = j >> 9, col = j & 511;
    const float* bb = (sel == 0) ? bq : (sel == 1) ? bk : bv;
    out[i] = bb[l * Cv + col];
}

// ---- warp-per-row layernorm: 8 rows/CTA, no smem, shfl-only ----
__global__ __launch_bounds__(256) void ln_k(const float* __restrict__ x,
                                            const float* __restrict__ g,
                                            const float* __restrict__ b,
                                            float* __restrict__ o)
{
    const int lane = threadIdx.x & 31;
    const int warp = threadIdx.x >> 5;
    const long row = (long)blockIdx.x * 8 + warp;
    const float* xr = x + row * Cv;

    float4 v[4];
#pragma unroll
    for (int j = 0; j < 4; j++) v[j] = *(const float4*)(xr + lane * 4 + j * 128);

    float s = 0.f, ss = 0.f;
#pragma unroll
    for (int j = 0; j < 4; j++) {
        s  += v[j].x + v[j].y + v[j].z + v[j].w;
        ss += v[j].x * v[j].x + v[j].y * v[j].y + v[j].z * v[j].z + v[j].w * v[j].w;
    }
#pragma unroll
    for (int off = 16; off > 0; off >>= 1) {
        s  += __shfl_xor_sync(0xffffffffu, s,  off);
        ss += __shfl_xor_sync(0xffffffffu, ss, off);
    }
    const float mu  = s * (1.f / Cv);
    const float var = ss * (1.f / Cv) - mu * mu;
    const float inv = rsqrtf(var + 1e-5f);

    float* orow = o + row * Cv;
#pragma unroll
    for (int j = 0; j < 4; j++) {
        const int c = lane * 4 + j * 128;
        float4 gv = *(const float4*)(g + c);
        float4 bb = *(const float4*)(b + c);
        float4 w;
        w.x = (v[j].x - mu) * inv * gv.x + bb.x;
        w.y = (v[j].y - mu) * inv * gv.y + bb.y;
        w.z = (v[j].z - mu) * inv * gv.z + bb.z;
        w.w = (v[j].w - mu) * inv * gv.w + bb.w;
        *(float4*)(orow + c) = w;
    }
}

// ---- tf32 GEMM 128x64 (proven) ----
template <bool GELU_ACT>
__global__ __launch_bounds__(256) void gemm_tc(
    const float* __restrict__ A, int lda,
    const float* __restrict__ Bm, int ldb,
    const float* __restrict__ bias,
    const float* __restrict__ res,
    float* __restrict__ Cm, int ldc,
    int K)
{
    extern __shared__ unsigned sm_[];
    unsigned* As = sm_;
    unsigned* Bs = sm_ + 2 * BM * ASTR;
#define AS(b,m,k) As[(((b)*BM) + (m))*ASTR + (k)]
#define BS(b,k,n) Bs[(((b)*BK) + (k))*BSTR + (n)]

    const int tid  = threadIdx.x;
    const int lane = tid & 31;
    const int wid  = tid >> 5;
    const int mWarp = (wid >> 1) * 32;
    const int nWarp = (wid & 1) * 32;
    const int rowBase = blockIdx.y * BM;
    const int colBase = blockIdx.x * BN;
    const int r  = lane >> 2;
    const int cq = lane & 3;

    float acc[2][4][4];
#pragma unroll
    for (int mi = 0; mi < 2; mi++)
#pragma unroll
        for (int ni = 0; ni < 4; ni++)
#pragma unroll
            for (int t = 0; t < 4; t++) acc[mi][ni][t] = 0.f;

    const int KT = K / BK;
    float4 ra[4];
    float4 rb[2];

    {
#pragma unroll
        for (int i = 0; i < 4; i++) {
            int f = tid + i * 256;
            int row = f >> 3, c4 = (f & 7) * 4;
            ra[i] = *(const float4*)(A + (long)(rowBase + row) * lda + c4);
        }
#pragma unroll
        for (int i = 0; i < 2; i++) {
            int f = tid + i * 256;
            int kk = f >> 4, n4 = (f & 15) * 4;
            rb[i] = *(const float4*)(Bm + (long)kk * ldb + colBase + n4);
        }
#pragma unroll
        for (int i = 0; i < 4; i++) {
            int f = tid + i * 256;
            int row = f >> 3, c4 = (f & 7) * 4;
            AS(0, row, c4 + 0) = f2tf(ra[i].x);
            AS(0, row, c4 + 1) = f2tf(ra[i].y);
            AS(0, row, c4 + 2) = f2tf(ra[i].z);
            AS(0, row, c4 + 3) = f2tf(ra[i].w);
        }
#pragma unroll
        for (int i = 0; i < 2; i++) {
            int f = tid + i * 256;
            int kk = f >> 4, n4 = (f & 15) * 4;
            uint4 s;
            s.x = f2tf(rb[i].x); s.y = f2tf(rb[i].y);
            s.z = f2tf(rb[i].z); s.w = f2tf(rb[i].w);
            *(uint4*)&BS(0, kk, n4) = s;
        }
    }
    __syncthreads();

    for (int kt = 0; kt < KT; kt++) {
        const int buf = kt & 1;
        const bool hasNext = (kt + 1 < KT);

        if (hasNext) {
            const int k0 = (kt + 1) * BK;
#pragma unroll
            for (int i = 0; i < 4; i++) {
                int f = tid + i * 256;
                int row = f >> 3, c4 = (f & 7) * 4;
                ra[i] = *(const float4*)(A + (long)(rowBase + row) * lda + k0 + c4);
            }
#pragma unroll
            for (int i = 0; i < 2; i++) {
                int f = tid + i * 256;
                int kk = f >> 4, n4 = (f & 15) * 4;
                rb[i] = *(const float4*)(Bm + (long)(k0 + kk) * ldb + colBase + n4);
            }
        }

#pragma unroll
        for (int ks = 0; ks < 4; ks++) {
            const int kb = ks * 8;
            unsigned a[2][4];
#pragma unroll
            for (int mi = 0; mi < 2; mi++) {
                int m = mWarp + mi * 16;
                a[mi][0] = AS(buf, m + r,     kb + cq);
                a[mi][1] = AS(buf, m + r + 8, kb + cq);
                a[mi][2] = AS(buf, m + r,     kb + cq + 4);
                a[mi][3] = AS(buf, m + r + 8, kb + cq + 4);
            }
            unsigned bb[4][2];
#pragma unroll
            for (int ni = 0; ni < 4; ni++) {
                int n = nWarp + ni * 8 + r;
                bb[ni][0] = BS(buf, kb + cq,     n);
                bb[ni][1] = BS(buf, kb + cq + 4, n);
            }
#pragma unroll
            for (int mi = 0; mi < 2; mi++)
#pragma unroll
                for (int ni = 0; ni < 4; ni++)
                    mma8(acc[mi][ni], a[mi][0], a[mi][1], a[mi][2], a[mi][3],
                         bb[ni][0], bb[ni][1]);
        }

        if (hasNext) {
            const int nb = buf ^ 1;
#pragma unroll
            for (int i = 0; i < 4; i++) {
                int f = tid + i * 256;
                int row = f >> 3, c4 = (f & 7) * 4;
                AS(nb, row, c4 + 0) = f2tf(ra[i].x);
                AS(nb, row, c4 + 1) = f2tf(ra[i].y);
                AS(nb, row, c4 + 2) = f2tf(ra[i].z);
                AS(nb, row, c4 + 3) = f2tf(ra[i].w);
            }
#pragma unroll
            for (int i = 0; i < 2; i++) {
                int f = tid + i * 256;
                int kk = f >> 4, n4 = (f & 15) * 4;
                uint4 s;
                s.x = f2tf(rb[i].x); s.y = f2tf(rb[i].y);
                s.z = f2tf(rb[i].z); s.w = f2tf(rb[i].w);
                *(uint4*)&BS(nb, kk, n4) = s;
            }
        }
        __syncthreads();
    }

#pragma unroll
    for (int mi = 0; mi < 2; mi++) {
#pragma unroll
        for (int ni = 0; ni < 4; ni++) {
            int row0 = rowBase + mWarp + mi * 16 + r;
            int col  = colBase + nWarp + ni * 8 + 2 * cq;
#pragma unroll
            for (int half = 0; half < 2; half++) {
                int rr = row0 + half * 8;
                float v0 = acc[mi][ni][half * 2 + 0];
                float v1 = acc[mi][ni][half * 2 + 1];
                if (bias) { v0 += bias[col]; v1 += bias[col + 1]; }
                if (res) {
                    float2 rv = *(const float2*)(res + (long)rr * ldc + col);
                    v0 += rv.x; v1 += rv.y;
                }
                if (GELU_ACT) {
                    v0 = 0.5f * v0 * (1.f + erff(v0 * 0.70710678118654752f));
                    v1 = 0.5f * v1 * (1.f + erff(v1 * 0.70710678118654752f));
                }
                float2 ov; ov.x = v0; ov.y = v1;
                *(float2*)(Cm + (long)rr * ldc + col) = ov;
            }
        }
    }
#undef AS
#undef BS
}

// ---- tf32 GEMM 128x128, warp tile 32x64 (more reuse per LDS) ----
template <bool GELU_ACT>
__global__ __launch_bounds__(256) void gemm_big(
    const float* __restrict__ A, int lda,
    const float* __restrict__ Bm, int ldb,
    const float* __restrict__ bias,
    const float* __restrict__ res,
    float* __restrict__ Cm, int ldc,
    int K)
{
    extern __shared__ unsigned sm_[];
    unsigned* As = sm_;                          // [2][BM][ASTR]
    unsigned* Bs = sm_ + 2 * BM * ASTR;          // [2][BK][BSTR2]
#define AS(b,m,k) As[(((b)*BM) + (m))*ASTR + (k)]
#define BS(b,k,n) Bs[(((b)*BK) + (k))*BSTR2 + (n)]

    const int tid  = threadIdx.x;
    const int lane = tid & 31;
    const int wid  = tid >> 5;
    const int mWarp = (wid >> 1) * 32;   // 4 m-warps
    const int nWarp = (wid & 1) * 64;    // 2 n-warps, 64 wide
    const int rowBase = blockIdx.y * BM;
    const int colBase = blockIdx.x * BN2;
    const int r  = lane >> 2;
    const int cq = lane & 3;

    float acc[2][8][4];
#pragma unroll
    for (int mi = 0; mi < 2; mi++)
#pragma unroll
        for (int ni = 0; ni < 8; ni++)
#pragma unroll
            for (int t = 0; t < 4; t++) acc[mi][ni][t] = 0.f;

    const int KT = K / BK;
    float4 ra[4];
    float4 rb[4];

    {
#pragma unroll
        for (int i = 0; i < 4; i++) {
            int f = tid + i * 256;
            int row = f >> 3, c4 = (f & 7) * 4;
            ra[i] = *(const float4*)(A + (long)(rowBase + row) * lda + c4);
        }
#pragma unroll
        for (int i = 0; i < 4; i++) {
            int f = tid + i * 256;
            int kk = f >> 5, n4 = (f & 31) * 4;
            rb[i] = *(const float4*)(Bm + (long)kk * ldb + colBase + n4);
        }
#pragma unroll
        for (int i = 0; i < 4; i++) {
            int f = tid + i * 256;
            int row = f >> 3, c4 = (f & 7) * 4;
            AS(0, row, c4 + 0) = f2tf(ra[i].x);
            AS(0, row, c4 + 1) = f2tf(ra[i].y);
            AS(0, row, c4 + 2) = f2tf(ra[i].z);
            AS(0, row, c4 + 3) = f2tf(ra[i].w);
        }
#pragma unroll
        for (int i = 0; i < 4; i++) {
            int f = tid + i * 256;
            int kk = f >> 5, n4 = (f & 31) * 4;
            uint4 s;
            s.x = f2tf(rb[i].x); s.y = f2tf(rb[i].y);
            s.z = f2tf(rb[i].z); s.w = f2tf(rb[i].w);
            *(uint4*)&BS(0, kk, n4) = s;
        }
    }
    __syncthreads();

    for (int kt = 0; kt < KT; kt++) {
        const int buf = kt & 1;
        const bool hasNext = (kt + 1 < KT);

        if (hasNext) {
            const int k0 = (kt + 1) * BK;
#pragma unroll
            for (int i = 0; i < 4; i++) {
                int f = tid + i * 256;
                int row = f >> 3, c4 = (f & 7) * 4;
                ra[i] = *(const float4*)(A + (long)(rowBase + row) * lda + k0 + c4);
            }
#pragma unroll
            for (int i = 0; i < 4; i++) {
                int f = tid + i * 256;
                int kk = f >> 5, n4 = (f & 31) * 4;
                rb[i] = *(const float4*)(Bm + (long)(k0 + kk) * ldb + colBase + n4);
            }
        }

#pragma unroll
        for (int ks = 0; ks < 4; ks++) {
            const int kb = ks * 8;
            unsigned a[2][4];
#pragma unroll
            for (int mi = 0; mi < 2; mi++) {
                int m = mWarp + mi * 16;
                a[mi][0] = AS(buf, m + r,     kb + cq);
                a[mi][1] = AS(buf, m + r + 8, kb + cq);
                a[mi][2] = AS(buf, m + r,     kb + cq + 4);
                a[mi][3] = AS(buf, m + r + 8, kb + cq + 4);
            }
            unsigned bb[8][2];
#pragma unroll
            for (int ni = 0; ni < 8; ni++) {
                int n = nWarp + ni * 8 + r;
                bb[ni][0] = BS(buf, kb + cq,     n);
                bb[ni][1] = BS(buf, kb + cq + 4, n);
            }
#pragma unroll
            for (int mi = 0; mi < 2; mi++)
#pragma unroll
                for (int ni = 0; ni < 8; ni++)
                    mma8(acc[mi][ni], a[mi][0], a[mi][1], a[mi][2], a[mi][3],
                         bb[ni][0], bb[ni][1]);
        }

        if (hasNext) {
            const int nb = buf ^ 1;
#pragma unroll
            for (int i = 0; i < 4; i++) {
                int f = tid + i * 256;
                int row = f >> 3, c4 = (f & 7) * 4;
                AS(nb, row, c4 + 0) = f2tf(ra[i].x);
                AS(nb, row, c4 + 1) = f2tf(ra[i].y);
                AS(nb, row, c4 + 2) = f2tf(ra[i].z);
                AS(nb, row, c4 + 3) = f2tf(ra[i].w);
            }
#pragma unroll
            for (int i = 0; i < 4; i++) {
                int f = tid + i * 256;
                int kk = f >> 5, n4 = (f & 31) * 4;
                uint4 s;
                s.x = f2tf(rb[i].x); s.y = f2tf(rb[i].y);
                s.z = f2tf(rb[i].z); s.w = f2tf(rb[i].w);
                *(uint4*)&BS(nb, kk, n4) = s;
            }
        }
        __syncthreads();
    }

#pragma unroll
    for (int mi = 0; mi < 2; mi++) {
#pragma unroll
        for (int ni = 0; ni < 8; ni++) {
            int row0 = rowBase + mWarp + mi * 16 + r;
            int col  = colBase + nWarp + ni * 8 + 2 * cq;
#pragma unroll
            for (int half = 0; half < 2; half++) {
                int rr = row0 + half * 8;
                float v0 = acc[mi][ni][half * 2 + 0];
                float v1 = acc[mi][ni][half * 2 + 1];
                if (bias) { v0 += bias[col]; v1 += bias[col + 1]; }
                if (res) {
                    float2 rv = *(const float2*)(res + (long)rr * ldc + col);
                    v0 += rv.x; v1 += rv.y;
                }
                if (GELU_ACT) {
                    v0 = 0.5f * v0 * (1.f + erff(v0 * 0.70710678118654752f));
                    v1 = 0.5f * v1 * (1.f + erff(v1 * 0.70710678118654752f));
                }
                float2 ov; ov.x = v0; ov.y = v1;
                *(float2*)(Cm + (long)rr * ldc + col) = ov;
            }
        }
    }
#undef AS
#undef BS
}

// ---- fused flash attention over packed QKV ----
__global__ __launch_bounds__(256) void attn_k(
    const float* __restrict__ qkv,
    float* __restrict__ y)
{
    extern __shared__ unsigned sm_[];
    unsigned* Qs = sm_;
    unsigned* Ks = Qs + QROWS * DSTR;
    unsigned* Vs = Ks + 2 * KTILE * DSTR;
    unsigned* Ps = Vs + 2 * KTILE * DSTR;

    const int tid  = threadIdx.x;
    const int lane = tid & 31;
    const int wid  = tid >> 5;
    const int r  = lane >> 2;
    const int cq = lane & 3;

    const int bh = blockIdx.y;
    const long base = (long)(bh >> 3) * Tv * QKVW + (bh & 7) * DHv;
    const float* q = qkv + base;
    const float* k = qkv + base + Cv;
    const float* v = qkv + base + 2 * Cv;
    const int q0 = blockIdx.x * QROWS;

    {
        int row = tid & 127;
        int d0  = (tid >> 7) * 32;
        const float* src = q + (long)(q0 + row) * QKVW + d0;
        float4 f[8];
#pragma unroll
        for (int u = 0; u < 8; u++) f[u] = *(const float4*)(src + 4 * u);
        unsigned* dst = Qs + row * DSTR + d0;
        const float* ff = (const float*)f;
#pragma unroll
        for (int e = 0; e < 4; e++) {
            uint4 s0, s1;
            s0.x = f2tf(ff[e] * SCALE);      s0.y = f2tf(ff[4 + e] * SCALE);
            s0.z = f2tf(ff[8 + e] * SCALE);  s0.w = f2tf(ff[12 + e] * SCALE);
            s1.x = f2tf(ff[16 + e] * SCALE); s1.y = f2tf(ff[20 + e] * SCALE);
            s1.z = f2tf(ff[24 + e] * SCALE); s1.w = f2tf(ff[28 + e] * SCALE);
            *(uint4*)(dst + e * 8)     = s0;
            *(uint4*)(dst + e * 8 + 4) = s1;
        }
    }

    const int krK = tid & 63;
    const int d0K = (tid >> 6) * 16;
    const int dV   = tid & 63;
    const int kr0V = (tid >> 6) * 16;

    float4 kf[4];
    float  vf[16];
    {
        const float* ks = k + (long)krK * QKVW + d0K;
#pragma unroll
        for (int u = 0; u < 4; u++) kf[u] = *(const float4*)(ks + 4 * u);
        const float* vs = v + (long)kr0V * QKVW + dV;
#pragma unroll
        for (int j = 0; j < 16; j++) vf[j] = vs[(long)j * QKVW];
    }
    {
        unsigned* kd = Ks + krK * DSTR + (d0K & 32) + 4 * ((d0K >> 4) & 1);
        const float* fk = (const float*)kf;
#pragma unroll
        for (int e = 0; e < 4; e++) {
            uint4 s;
            s.x = f2tf(fk[e]); s.y = f2tf(fk[4 + e]);
            s.z = f2tf(fk[8 + e]); s.w = f2tf(fk[12 + e]);
            *(uint4*)(kd + e * 8) = s;
        }
        unsigned* vd = Vs + dV * DSTR + (kr0V & 32) + 4 * ((kr0V >> 4) & 1);
#pragma unroll
        for (int e = 0; e < 4; e++) {
            uint4 s;
            s.x = f2tf(vf[e]); s.y = f2tf(vf[4 + e]);
            s.z = f2tf(vf[8 + e]); s.w = f2tf(vf[12 + e]);
            *(uint4*)(vd + e * 8) = s;
        }
    }
    __syncthreads();

    float o[8][4];
#pragma unroll
    for (int nf = 0; nf < 8; nf++)
#pragma unroll
        for (int t = 0; t < 4; t++) o[nf][t] = 0.f;
    float lp0 = 0.f, lp1 = 0.f;

    const int v0i = 2 * cq, v1i = 2 * cq + 1;
    const int pv0 = (v0i & 3) * 8 + (v0i >> 2);
    const int pv1 = (v1i & 3) * 8 + (v1i >> 2);
    const int qrow0 = wid * 16 + r;

    for (int t = 0; t < 8; t++) {
        const int buf = t & 1;
        const bool hasNext = (t < 7);

        if (hasNext) {
            const float* ks = k + (long)((t + 1) * 64 + krK) * QKVW + d0K;
#pragma unroll
            for (int u = 0; u < 4; u++) kf[u] = *(const float4*)(ks + 4 * u);
            const float* vs = v + (long)((t + 1) * 64 + kr0V) * QKVW + dV;
#pragma unroll
            for (int j = 0; j < 16; j++) vf[j] = vs[(long)j * QKVW];
        }

        float s[8][4];
#pragma unroll
        for (int nf = 0; nf < 8; nf++)
#pragma unroll
            for (int c = 0; c < 4; c++) s[nf][c] = 0.f;

        const unsigned* Kb = Ks + buf * KTILE * DSTR;
#pragma unroll
        for (int blk = 0; blk < 2; blk++) {
#pragma unroll
            for (int g = 0; g < 2; g++) {
                const int off = blk * 32 + cq * 8 + 4 * g;
                uint4 aA = *(const uint4*)(Qs + (qrow0)     * DSTR + off);
                uint4 aB = *(const uint4*)(Qs + (qrow0 + 8) * DSTR + off);
#pragma unroll
                for (int nf = 0; nf < 8; nf++) {
                    uint4 bb = *(const uint4*)(Kb + (nf * 8 + r) * DSTR + off);
                    mma8(s[nf], aA.x, aB.x, aA.y, aB.y, bb.x, bb.y);
                    mma8(s[nf], aA.z, aB.z, aA.w, aB.w, bb.z, bb.w);
                }
            }
        }

#pragma unroll
        for (int nf = 0; nf < 8; nf++) {
            float e0 = __expf(s[nf][0]);
            float e1 = __expf(s[nf][1]);
            float e2 = __expf(s[nf][2]);
            float e3 = __expf(s[nf][3]);
            lp0 += e0 + e1;
            lp1 += e2 + e3;
            unsigned* pr0 = Ps + (qrow0)     * DSTR + (nf >> 2) * 32 + 2 * (nf & 3);
            unsigned* pr1 = Ps + (qrow0 + 8) * DSTR + (nf >> 2) * 32 + 2 * (nf & 3);
            pr0[pv0] = f2tf(e0); pr0[pv1] = f2tf(e1);
            pr1[pv0] = f2tf(e2); pr1[pv1] = f2tf(e3);
        }
        __syncwarp();

        const unsigned* Vb = Vs + buf * KTILE * DSTR;
#pragma unroll
        for (int blk = 0; blk < 2; blk++) {
#pragma unroll
            for (int g = 0; g < 2; g++) {
                const int off = blk * 32 + cq * 8 + 4 * g;
                uint4 aA = *(const uint4*)(Ps + (qrow0)     * DSTR + off);
                uint4 aB = *(const uint4*)(Ps + (qrow0 + 8) * DSTR + off);
#pragma unroll
                for (int nf = 0; nf < 8; nf++) {
                    uint4 bb = *(const uint4*)(Vb + (nf * 8 + r) * DSTR + off);
                    mma8(o[nf], aA.x, aB.x, aA.y, aB.y, bb.x, bb.y);
                    mma8(o[nf], aA.z, aB.z, aA.w, aB.w, bb.z, bb.w);
                }
            }
        }

        if (hasNext) {
            const int nb = buf ^ 1;
            unsigned* kd = Ks + nb * KTILE * DSTR + krK * DSTR + (d0K & 32) + 4 * ((d0K >> 4) & 1);
            const float* fk = (const float*)kf;
#pragma unroll
            for (int e = 0; e < 4; e++) {
                uint4 ss;
                ss.x = f2tf(fk[e]); ss.y = f2tf(fk[4 + e]);
                ss.z = f2tf(fk[8 + e]); ss.w = f2tf(fk[12 + e]);
                *(uint4*)(kd + e * 8) = ss;
            }
            unsigned* vd = Vs + nb * KTILE * DSTR + dV * DSTR + (kr0V & 32) + 4 * ((kr0V >> 4) & 1);
#pragma unroll
            for (int e = 0; e < 4; e++) {
                uint4 ss;
                ss.x = f2tf(vf[e]); ss.y = f2tf(vf[4 + e]);
                ss.z = f2tf(vf[8 + e]); ss.w = f2tf(vf[12 + e]);
                *(uint4*)(vd + e * 8) = ss;
            }
        }
        __syncthreads();
    }

    lp0 += __shfl_xor_sync(0xffffffffu, lp0, 1);
    lp0 += __shfl_xor_sync(0xffffffffu, lp0, 2);
    lp1 += __shfl_xor_sync(0xffffffffu, lp1, 1);
    lp1 += __shfl_xor_sync(0xffffffffu, lp1, 2);
    const float i0 = 1.f / lp0;
    const float i1 = 1.f / lp1;

    const long outRow0 = (long)(bh >> 3) * Tv + q0 + qrow0;
    const int  colB = (bh & 7) * DHv;
#pragma unroll
    for (int nf = 0; nf < 8; nf++) {
        int col = colB + nf * 8 + 2 * cq;
        float2 w0; w0.x = o[nf][0] * i0; w0.y = o[nf][1] * i0;
        float2 w1; w1.x = o[nf][2] * i1; w1.y = o[nf][3] * i1;
        *(float2*)(y + (outRow0)     * Cv + col) = w0;
        *(float2*)(y + (outRow0 + 8) * Cv + col) = w1;
    }
}

extern "C" void kernel_launch(void* const* d_in, const int* in_sizes, int n_in,
                              void* d_out, int out_size)
{
    const int*   idx   = (const int*)  d_in[0];
    const float* tok   = (const float*)d_in[1];
    const float* pos   = (const float*)d_in[2];
    const float* ln1g  = (const float*)d_in[3];
    const float* ln1b  = (const float*)d_in[4];
    const float* Wq    = (const float*)d_in[5];
    const float* bq    = (const float*)d_in[6];
    const float* Wk    = (const float*)d_in[7];
    const float* bk    = (const float*)d_in[8];
    const float* Wv    = (const float*)d_in[9];
    const float* bv    = (const float*)d_in[10];
    const float* Wp    = (const float*)d_in[11];
    const float* bp    = (const float*)d_in[12];
    const float* ln2g  = (const float*)d_in[13];
    const float* ln2b  = (const float*)d_in[14];
    const float* W1    = (const float*)d_in[15];
    const float* b1    = (const float*)d_in[16];
    const float* W2    = (const float*)d_in[17];
    const float* b2    = (const float*)d_in[18];
    const float* lnfg  = (const float*)d_in[19];
    const float* lnfb  = (const float*)d_in[20];
    const float* Whead = (const float*)d_in[21];
    float* out = (float*)d_out;

    float *x, *xn, *qkv, *y, *h, *wqkv, *bqkv;
    cudaGetSymbolAddress((void**)&x,    g_x);
    cudaGetSymbolAddress((void**)&xn,   g_xn);
    cudaGetSymbolAddress((void**)&qkv,  g_qkv);
    cudaGetSymbolAddress((void**)&y,    g_y);
    cudaGetSymbolAddress((void**)&h,    g_h);
    cudaGetSymbolAddress((void**)&wqkv, g_wqkv);
    cudaGetSymbolAddress((void**)&bqkv, g_bqkv);

    cudaFuncSetAttribute(gemm_tc<false>,
                         cudaFuncAttributeMaxDynamicSharedMemorySize, SMEM_BYTES);
    cudaFuncSetAttribute(gemm_tc<true>,
                         cudaFuncAttributeMaxDynamicSharedMemorySize, SMEM_BYTES);
    cudaFuncSetAttribute(gemm_big<false>,
                         cudaFuncAttributeMaxDynamicSharedMemorySize, SMEM2_BYTES);
    cudaFuncSetAttribute(gemm_big<true>,
                         cudaFuncAttributeMaxDynamicSharedMemorySize, SMEM2_BYTES);
    cudaFuncSetAttribute(attn_k,
                         cudaFuncAttributeMaxDynamicSharedMemorySize, ATT_SMEM_BYTES);

    pack_w_k<<<(Lv * Cv * QKVW) / 256, 256>>>(Wq, Wk, Wv, wqkv);
    pack_b_k<<<(Lv * QKVW) / 256, 256>>>(bq, bk, bv, bqkv);
    embed_k<<<(MALL * Cv) / 256, 256>>>(idx, tok, pos, x);

    for (int s = 0; s < STEPS; s++) {
        for (int l = 0; l < Lv; l++) {
            const float* wqkv_l = wqkv + (long)l * Cv * QKVW;
            const float* bqkv_l = bqkv + (long)l * QKVW;
            const float* wp = Wp + (long)l * Cv * Cv;
            const float* w1 = W1 + (long)l * Cv * FFv;
            const float* w2 = W2 + (long)l * FFv * Cv;

            ln_k<<<MALL / 8, 256>>>(x, ln1g + l * Cv, ln1b + l * Cv, xn);

            dim3 gQKV(QKVW / BN2, MALL / BM, 1);
            gemm_big<false><<<gQKV, 256, SMEM2_BYTES>>>(
                xn, Cv, wqkv_l, QKVW, bqkv_l, nullptr, qkv, QKVW, Cv);

            dim3 gAtt(Tv / QROWS, Bv * Hv, 1);
            attn_k<<<gAtt, 256, ATT_SMEM_BYTES>>>(qkv, y);

            dim3 gProj(Cv / BN, MALL / BM, 1);
            gemm_tc<false><<<gProj, 256, SMEM_BYTES>>>(
                y, Cv, wp, Cv, bp + l * Cv, x, x, Cv, Cv);

            ln_k<<<MALL / 8, 256>>>(x, ln2g + l * Cv, ln2b + l * Cv, xn);

            dim3 gFF1(FFv / BN2, MALL / BM, 1);
            gemm_big<true><<<gFF1, 256, SMEM2_BYTES>>>(
                xn, Cv, w1, FFv, b1 + l * FFv, nullptr, h, FFv, Cv);

            dim3 gFF2(Cv / BN2, MALL / BM, 1);
            gemm_big<false><<<gFF2, 256, SMEM2_BYTES>>>(
                h, FFv, w2, Cv, b2 + l * Cv, x, x, Cv, FFv);
        }
    }

    ln_k<<<MALL / 8, 256>>>(x, lnfg, lnfb, xn);
    dim3 gHead(Vv / BN, MALL / BM, 1);
    gemm_tc<false><<<gHead, 256, SMEM_BYTES>>>(
        xn, Cv, Whead, Vv, nullptr, nullptr, out, Vv, Cv);
}

// round 8
// speedup vs baseline: 1.6372x; 1.1366x over previous
#include <cuda_runtime.h>
#include <math.h>

#define Bv    8
#define Tv    512
#define Cv    512
#define Hv    8
#define DHv   64
#define Lv    2
#define Vv    512
#define FFv   2048
#define STEPS 4
#define MALL  (Bv*Tv)
#define SCALE 0.125f
#define QKVW  1536

#define BM 128
#define BN 64
#define BK 32
#define ASTR (BK + 4)
#define BSTR (BN + 8)
#define SMEM_BYTES ((2*BM*ASTR + 2*BK*BSTR) * 4)

#define BN2 128
#define BSTR2 (BN2 + 8)
#define NSTAGE 3
#define SMEM_CA_BYTES (NSTAGE*(BM*ASTR + BK*BSTR2)*4)   // 107520

#define QROWS 128
#define KTILE 64
#define DSTR  68
#define ATT_SMEM_BYTES ((2*QROWS*DSTR + 4*KTILE*DSTR)*4)

__device__ float g_x  [MALL*Cv];
__device__ float g_xn [MALL*Cv];
__device__ float g_qkv[MALL*QKVW];
__device__ float g_y  [MALL*Cv];
__device__ float g_h  [MALL*FFv];
__device__ float g_wqkv[Lv*Cv*QKVW];
__device__ float g_bqkv[Lv*QKVW];
__device__ float g_w1t[Lv*Cv*FFv];
__device__ float g_w2t[Lv*FFv*Cv];

__device__ __forceinline__ unsigned f2tf(float f)
{
    unsigned u;
    asm("cvt.rna.tf32.f32 %0, %1;" : "=r"(u) : "f"(f));
    return u;
}
__device__ __forceinline__ float f2tff(float f)
{
    return __uint_as_float(f2tf(f));
}

__device__ __forceinline__ void mma8(float acc[4],
                                     unsigned a0, unsigned a1, unsigned a2, unsigned a3,
                                     unsigned b0, unsigned b1)
{
    asm volatile(
        "mma.sync.aligned.m16n8k8.row.col.f32.tf32.tf32.f32 "
        "{%0,%1,%2,%3}, {%4,%5,%6,%7}, {%8,%9}, {%0,%1,%2,%3};\n"
        : "+f"(acc[0]), "+f"(acc[1]), "+f"(acc[2]), "+f"(acc[3])
        : "r"(a0), "r"(a1), "r"(a2), "r"(a3), "r"(b0), "r"(b1));
}

__device__ __forceinline__ void cp16(unsigned dst, const void* src)
{
    asm volatile("cp.async.cg.shared.global [%0], [%1], 16;" :: "r"(dst), "l"(src));
}

__global__ void embed_k(const int* __restrict__ idx,
                        const float* __restrict__ tok,
                        const float* __restrict__ pos,
                        float* __restrict__ x)
{
    int i = blockIdx.x * 256 + threadIdx.x;
    int c  = i & (Cv - 1);
    int bt = i >> 9;
    int t  = bt & (Tv - 1);
    x[i] = tok[idx[bt] * Cv + c] + pos[t * Cv + c];
}

__global__ void pack_w_k(const float* __restrict__ Wq,
                         const float* __restrict__ Wk,
                         const float* __restrict__ Wv,
                         float* __restrict__ out)
{
    int i = blockIdx.x * 256 + threadIdx.x;
    int j = i % QKVW;
    int rem = i / QKVW;
    int kk = rem % Cv;
    int l  = rem / Cv;
    int sel = j >> 9, col = j & 511;
    const float* W = (sel == 0) ? Wq : (sel == 1) ? Wk : Wv;
    out[i] = f2tff(W[((long)l * Cv + kk) * Cv + col]);
}

__global__ void pack_b_k(const float* __restrict__ bq,
                         const float* __restrict__ bk,
                         const float* __restrict__ bv,
                         float* __restrict__ out)
{
    int i = blockIdx.x * 256 + threadIdx.x;
    int j = i % QKVW;
    int l = i / QKVW;
    int sel = j >> 9, col = j & 511;
    const float* bb = (sel == 0) ? bq : (sel == 1) ? bk : bv;
    out[i] = bb[l * Cv + col];
}

__global__ void cvt_k(const float* __restrict__ in, float* __restrict__ out)
{
    int i = blockIdx.x * 256 + threadIdx.x;
    float4 v = *(const float4*)(in + i * 4);
    float4 w;
    w.x = f2tff(v.x); w.y = f2tff(v.y); w.z = f2tff(v.z); w.w = f2tff(v.w);
    *(float4*)(out + i * 4) = w;
}

// ---- warp-per-row layernorm; output tf32-rounded ----
__global__ __launch_bounds__(256) void ln_k(const float* __restrict__ x,
                                            const float* __restrict__ g,
                                            const float* __restrict__ b,
                                            float* __restrict__ o)
{
    const int lane = threadIdx.x & 31;
    const int warp = threadIdx.x >> 5;
    const long row = (long)blockIdx.x * 8 + warp;
    const float* xr = x + row * Cv;

    float4 v[4];
#pragma unroll
    for (int j = 0; j < 4; j++) v[j] = *(const float4*)(xr + lane * 4 + j * 128);

    float s = 0.f, ss = 0.f;
#pragma unroll
    for (int j = 0; j < 4; j++) {
        s  += v[j].x + v[j].y + v[j].z + v[j].w;
        ss += v[j].x * v[j].x + v[j].y * v[j].y + v[j].z * v[j].z + v[j].w * v[j].w;
    }
#pragma unroll
    for (int off = 16; off > 0; off >>= 1) {
        s  += __shfl_xor_sync(0xffffffffu, s,  off);
        ss += __shfl_xor_sync(0xffffffffu, ss, off);
    }
    const float mu  = s * (1.f / Cv);
    const float var = ss * (1.f / Cv) - mu * mu;
    const float inv = rsqrtf(var + 1e-5f);

    float* orow = o + row * Cv;
#pragma unroll
    for (int j = 0; j < 4; j++) {
        const int c = lane * 4 + j * 128;
        float4 gv = *(const float4*)(g + c);
        float4 bb = *(const float4*)(b + c);
        float4 w;
        w.x = f2tff((v[j].x - mu) * inv * gv.x + bb.x);
        w.y = f2tff((v[j].y - mu) * inv * gv.y + bb.y);
        w.z = f2tff((v[j].z - mu) * inv * gv.z + bb.z);
        w.w = f2tff((v[j].w - mu) * inv * gv.w + bb.w);
        *(float4*)(orow + c) = w;
    }
}

// ---- tf32 GEMM 128x64 (proven; does its own cvt) ----
template <bool GELU_ACT>
__global__ __launch_bounds__(256) void gemm_tc(
    const float* __restrict__ A, int lda,
    const float* __restrict__ Bm, int ldb,
    const float* __restrict__ bias,
    const float* __restrict__ res,
    float* __restrict__ Cm, int ldc,
    int K)
{
    extern __shared__ unsigned sm_[];
    unsigned* As = sm_;
    unsigned* Bs = sm_ + 2 * BM * ASTR;
#define AS(b,m,k) As[(((b)*BM) + (m))*ASTR + (k)]
#define BS(b,k,n) Bs[(((b)*BK) + (k))*BSTR + (n)]

    const int tid  = threadIdx.x;
    const int lane = tid & 31;
    const int wid  = tid >> 5;
    const int mWarp = (wid >> 1) * 32;
    const int nWarp = (wid & 1) * 32;
    const int rowBase = blockIdx.y * BM;
    const int colBase = blockIdx.x * BN;
    const int r  = lane >> 2;
    const int cq = lane & 3;

    float acc[2][4][4];
#pragma unroll
    for (int mi = 0; mi < 2; mi++)
#pragma unroll
        for (int ni = 0; ni < 4; ni++)
#pragma unroll
            for (int t = 0; t < 4; t++) acc[mi][ni][t] = 0.f;

    const int KT = K / BK;
    float4 ra[4];
    float4 rb[2];

    {
#pragma unroll
        for (int i = 0; i < 4; i++) {
            int f = tid + i * 256;
            int row = f >> 3, c4 = (f & 7) * 4;
            ra[i] = *(const float4*)(A + (long)(rowBase + row) * lda + c4);
        }
#pragma unroll
        for (int i = 0; i < 2; i++) {
            int f = tid + i * 256;
            int kk = f >> 4, n4 = (f & 15) * 4;
            rb[i] = *(const float4*)(Bm + (long)kk * ldb + colBase + n4);
        }
#pragma unroll
        for (int i = 0; i < 4; i++) {
            int f = tid + i * 256;
            int row = f >> 3, c4 = (f & 7) * 4;
            AS(0, row, c4 + 0) = f2tf(ra[i].x);
            AS(0, row, c4 + 1) = f2tf(ra[i].y);
            AS(0, row, c4 + 2) = f2tf(ra[i].z);
            AS(0, row, c4 + 3) = f2tf(ra[i].w);
        }
#pragma unroll
        for (int i = 0; i < 2; i++) {
            int f = tid + i * 256;
            int kk = f >> 4, n4 = (f & 15) * 4;
            uint4 s;
            s.x = f2tf(rb[i].x); s.y = f2tf(rb[i].y);
            s.z = f2tf(rb[i].z); s.w = f2tf(rb[i].w);
            *(uint4*)&BS(0, kk, n4) = s;
        }
    }
    __syncthreads();

    for (int kt = 0; kt < KT; kt++) {
        const int buf = kt & 1;
        const bool hasNext = (kt + 1 < KT);

        if (hasNext) {
            const int k0 = (kt + 1) * BK;
#pragma unroll
            for (int i = 0; i < 4; i++) {
                int f = tid + i * 256;
                int row = f >> 3, c4 = (f & 7) * 4;
                ra[i] = *(const float4*)(A + (long)(rowBase + row) * lda + k0 + c4);
            }
#pragma unroll
            for (int i = 0; i < 2; i++) {
                int f = tid + i * 256;
                int kk = f >> 4, n4 = (f & 15) * 4;
                rb[i] = *(const float4*)(Bm + (long)(k0 + kk) * ldb + colBase + n4);
            }
        }

#pragma unroll
        for (int ks = 0; ks < 4; ks++) {
            const int kb = ks * 8;
            unsigned a[2][4];
#pragma unroll
            for (int mi = 0; mi < 2; mi++) {
                int m = mWarp + mi * 16;
                a[mi][0] = AS(buf, m + r,     kb + cq);
                a[mi][1] = AS(buf, m + r + 8, kb + cq);
                a[mi][2] = AS(buf, m + r,     kb + cq + 4);
                a[mi][3] = AS(buf, m + r + 8, kb + cq + 4);
            }
            unsigned bb[4][2];
#pragma unroll
            for (int ni = 0; ni < 4; ni++) {
                int n = nWarp + ni * 8 + r;
                bb[ni][0] = BS(buf, kb + cq,     n);
                bb[ni][1] = BS(buf, kb + cq + 4, n);
            }
#pragma unroll
            for (int mi = 0; mi < 2; mi++)
#pragma unroll
                for (int ni = 0; ni < 4; ni++)
                    mma8(acc[mi][ni], a[mi][0], a[mi][1], a[mi][2], a[mi][3],
                         bb[ni][0], bb[ni][1]);
        }

        if (hasNext) {
            const int nb = buf ^ 1;
#pragma unroll
            for (int i = 0; i < 4; i++) {
                int f = tid + i * 256;
                int row = f >> 3, c4 = (f & 7) * 4;
                AS(nb, row, c4 + 0) = f2tf(ra[i].x);
                AS(nb, row, c4 + 1) = f2tf(ra[i].y);
                AS(nb, row, c4 + 2) = f2tf(ra[i].z);
                AS(nb, row, c4 + 3) = f2tf(ra[i].w);
            }
#pragma unroll
            for (int i = 0; i < 2; i++) {
                int f = tid + i * 256;
                int kk = f >> 4, n4 = (f & 15) * 4;
                uint4 s;
                s.x = f2tf(rb[i].x); s.y = f2tf(rb[i].y);
                s.z = f2tf(rb[i].z); s.w = f2tf(rb[i].w);
                *(uint4*)&BS(nb, kk, n4) = s;
            }
        }
        __syncthreads();
    }

#pragma unroll
    for (int mi = 0; mi < 2; mi++) {
#pragma unroll
        for (int ni = 0; ni < 4; ni++) {
            int row0 = rowBase + mWarp + mi * 16 + r;
            int col  = colBase + nWarp + ni * 8 + 2 * cq;
#pragma unroll
            for (int half = 0; half < 2; half++) {
                int rr = row0 + half * 8;
                float v0 = acc[mi][ni][half * 2 + 0];
                float v1 = acc[mi][ni][half * 2 + 1];
                if (bias) { v0 += bias[col]; v1 += bias[col + 1]; }
                if (res) {
                    float2 rv = *(const float2*)(res + (long)rr * ldc + col);
                    v0 += rv.x; v1 += rv.y;
                }
                if (GELU_ACT) {
                    v0 = 0.5f * v0 * (1.f + erff(v0 * 0.70710678118654752f));
                    v1 = 0.5f * v1 * (1.f + erff(v1 * 0.70710678118654752f));
                }
                float2 ov; ov.x = v0; ov.y = v1;
                *(float2*)(Cm + (long)rr * ldc + col) = ov;
            }
        }
    }
#undef AS
#undef BS
}

// ---- tf32 GEMM 128x128, cp.async 3-stage, inputs pre-rounded to tf32 ----
template <bool GELU_ACT, bool ROUND_OUT>
__global__ __launch_bounds__(256) void gemm_ca(
    const float* __restrict__ A, int lda,
    const float* __restrict__ Bm, int ldb,
    const float* __restrict__ bias,
    const float* __restrict__ res,
    float* __restrict__ Cm, int ldc,
    int K)
{
    extern __shared__ unsigned sm_[];
    unsigned* As = sm_;                          // [NSTAGE][BM][ASTR]
    unsigned* Bs = sm_ + NSTAGE * BM * ASTR;     // [NSTAGE][BK][BSTR2]

    const int tid  = threadIdx.x;
    const int lane = tid & 31;
    const int wid  = tid >> 5;
    const int mWarp = (wid >> 1) * 32;
    const int nWarp = (wid & 1) * 64;
    const int rowBase = blockIdx.y * BM;
    const int colBase = blockIdx.x * BN2;
    const int r  = lane >> 2;
    const int cq = lane & 3;

    const unsigned smem_u32 = (unsigned)__cvta_generic_to_shared(sm_);
    const unsigned bbase = smem_u32 + NSTAGE * BM * ASTR * 4;

    float acc[2][8][4];
#pragma unroll
    for (int mi = 0; mi < 2; mi++)
#pragma unroll
        for (int ni = 0; ni < 8; ni++)
#pragma unroll
            for (int t = 0; t < 4; t++) acc[mi][ni][t] = 0.f;

    const int KT = K / BK;

    // loader thread mapping (constant per thread)
    const int arow = tid >> 1;              // 0..127
    const int ac4  = (tid & 1) * 16;        // two 16B chunks => covers 32 k? no: need 4 ops
    (void)arow; (void)ac4;

#define LOAD_STAGE(s, k0)                                                        \
    {                                                                            \
        _Pragma("unroll")                                                        \
        for (int i = 0; i < 4; i++) {                                            \
            int f = tid + i * 256;                                               \
            int row = f >> 3, c4 = (f & 7) * 4;                                  \
            cp16(smem_u32 + (((s) * BM + row) * ASTR + c4) * 4,                  \
                 A + (long)(rowBase + row) * lda + (k0) + c4);                   \
        }                                                                        \
        _Pragma("unroll")                                                        \
        for (int i = 0; i < 4; i++) {                                            \
            int f = tid + i * 256;                                               \
            int kk = f >> 5, n4 = (f & 31) * 4;                                  \
            cp16(bbase + (((s) * BK + kk) * BSTR2 + n4) * 4,                     \
                 Bm + (long)((k0) + kk) * ldb + colBase + n4);                   \
        }                                                                        \
        asm volatile("cp.async.commit_group;");                                  \
    }

    LOAD_STAGE(0, 0);
    LOAD_STAGE(1, BK);

    for (int kt = 0; kt < KT; kt++) {
        if (kt + 1 < KT) asm volatile("cp.async.wait_group 1;");
        else             asm volatile("cp.async.wait_group 0;");
        __syncthreads();

        const int buf = kt % NSTAGE;
        if (kt + 2 < KT) {
            const int s2 = (kt + 2) % NSTAGE;
            const int k2 = (kt + 2) * BK;
            LOAD_STAGE(s2, k2);
        }

        const unsigned* Ab = As + buf * BM * ASTR;
        const unsigned* Bb = Bs + buf * BK * BSTR2;
#pragma unroll
        for (int ks = 0; ks < 4; ks++) {
            const int kb = ks * 8;
            unsigned a[2][4];
#pragma unroll
            for (int mi = 0; mi < 2; mi++) {
                int m = mWarp + mi * 16;
                a[mi][0] = Ab[(m + r)     * ASTR + kb + cq];
                a[mi][1] = Ab[(m + r + 8) * ASTR + kb + cq];
                a[mi][2] = Ab[(m + r)     * ASTR + kb + cq + 4];
                a[mi][3] = Ab[(m + r + 8) * ASTR + kb + cq + 4];
            }
            unsigned bb[8][2];
#pragma unroll
            for (int ni = 0; ni < 8; ni++) {
                int n = nWarp + ni * 8 + r;
                bb[ni][0] = Bb[(kb + cq)     * BSTR2 + n];
                bb[ni][1] = Bb[(kb + cq + 4) * BSTR2 + n];
            }
#pragma unroll
            for (int mi = 0; mi < 2; mi++)
#pragma unroll
                for (int ni = 0; ni < 8; ni++)
                    mma8(acc[mi][ni], a[mi][0], a[mi][1], a[mi][2], a[mi][3],
                         bb[ni][0], bb[ni][1]);
        }
        __syncthreads();
    }
#undef LOAD_STAGE

#pragma unroll
    for (int mi = 0; mi < 2; mi++) {
#pragma unroll
        for (int ni = 0; ni < 8; ni++) {
            int row0 = rowBase + mWarp + mi * 16 + r;
            int col  = colBase + nWarp + ni * 8 + 2 * cq;
#pragma unroll
            for (int half = 0; half < 2; half++) {
                int rr = row0 + half * 8;
                float v0 = acc[mi][ni][half * 2 + 0];
                float v1 = acc[mi][ni][half * 2 + 1];
                if (bias) { v0 += bias[col]; v1 += bias[col + 1]; }
                if (res) {
                    float2 rv = *(const float2*)(res + (long)rr * ldc + col);
                    v0 += rv.x; v1 += rv.y;
                }
                if (GELU_ACT) {
                    v0 = 0.5f * v0 * (1.f + erff(v0 * 0.70710678118654752f));
                    v1 = 0.5f * v1 * (1.f + erff(v1 * 0.70710678118654752f));
                }
                if (ROUND_OUT) { v0 = f2tff(v0); v1 = f2tff(v1); }
                float2 ov; ov.x = v0; ov.y = v1;
                *(float2*)(Cm + (long)rr * ldc + col) = ov;
            }
        }
    }
}

// ---- fused flash attention over packed QKV (inputs tf32-rounded) ----
__global__ __launch_bounds__(256) void attn_k(
    const float* __restrict__ qkv,
    float* __restrict__ y)
{
    extern __shared__ unsigned sm_[];
    unsigned* Qs = sm_;
    unsigned* Ks = Qs + QROWS * DSTR;
    unsigned* Vs = Ks + 2 * KTILE * DSTR;
    unsigned* Ps = Vs + 2 * KTILE * DSTR;

    const int tid  = threadIdx.x;
    const int lane = tid & 31;
    const int wid  = tid >> 5;
    const int r  = lane >> 2;
    const int cq = lane & 3;

    const int bh = blockIdx.y;
    const long base = (long)(bh >> 3) * Tv * QKVW + (bh & 7) * DHv;
    const float* q = qkv + base;
    const float* k = qkv + base + Cv;
    const float* v = qkv + base + 2 * Cv;
    const int q0 = blockIdx.x * QROWS;

    {
        int row = tid & 127;
        int d0  = (tid >> 7) * 32;
        const float* src = q + (long)(q0 + row) * QKVW + d0;
        float4 f[8];
#pragma unroll
        for (int u = 0; u < 8; u++) f[u] = *(const float4*)(src + 4 * u);
        unsigned* dst = Qs + row * DSTR + d0;
        const float* ff = (const float*)f;
#pragma unroll
        for (int e = 0; e < 4; e++) {
            uint4 s0, s1;
            s0.x = f2tf(ff[e] * SCALE);      s0.y = f2tf(ff[4 + e] * SCALE);
            s0.z = f2tf(ff[8 + e] * SCALE);  s0.w = f2tf(ff[12 + e] * SCALE);
            s1.x = f2tf(ff[16 + e] * SCALE); s1.y = f2tf(ff[20 + e] * SCALE);
            s1.z = f2tf(ff[24 + e] * SCALE); s1.w = f2tf(ff[28 + e] * SCALE);
            *(uint4*)(dst + e * 8)     = s0;
            *(uint4*)(dst + e * 8 + 4) = s1;
        }
    }

    const int krK = tid & 63;
    const int d0K = (tid >> 6) * 16;
    const int dV   = tid & 63;
    const int kr0V = (tid >> 6) * 16;

    float4 kf[4];
    float  vf[16];
    {
        const float* ks = k + (long)krK * QKVW + d0K;
#pragma unroll
        for (int u = 0; u < 4; u++) kf[u] = *(const float4*)(ks + 4 * u);
        const float* vs = v + (long)kr0V * QKVW + dV;
#pragma unroll
        for (int j = 0; j < 16; j++) vf[j] = vs[(long)j * QKVW];
    }
    {
        unsigned* kd = Ks + krK * DSTR + (d0K & 32) + 4 * ((d0K >> 4) & 1);
        const float* fk = (const float*)kf;
#pragma unroll
        for (int e = 0; e < 4; e++) {
            uint4 s;
            s.x = f2tf(fk[e]); s.y = f2tf(fk[4 + e]);
            s.z = f2tf(fk[8 + e]); s.w = f2tf(fk[12 + e]);
            *(uint4*)(kd + e * 8) = s;
        }
        unsigned* vd = Vs + dV * DSTR + (kr0V & 32) + 4 * ((kr0V >> 4) & 1);
#pragma unroll
        for (int e = 0; e < 4; e++) {
            uint4 s;
            s.x = f2tf(vf[e]); s.y = f2tf(vf[4 + e]);
            s.z = f2tf(vf[8 + e]); s.w = f2tf(vf[12 + e]);
            *(uint4*)(vd + e * 8) = s;
        }
    }
    __syncthreads();

    float o[8][4];
#pragma unroll
    for (int nf = 0; nf < 8; nf++)
#pragma unroll
        for (int t = 0; t < 4; t++) o[nf][t] = 0.f;
    float lp0 = 0.f, lp1 = 0.f;

    const int v0i = 2 * cq, v1i = 2 * cq + 1;
    const int pv0 = (v0i & 3) * 8 + (v0i >> 2);
    const int pv1 = (v1i & 3) * 8 + (v1i >> 2);
    const int qrow0 = wid * 16 + r;

    for (int t = 0; t < 8; t++) {
        const int buf = t & 1;
        const bool hasNext = (t < 7);

        if (hasNext) {
            const float* ks = k + (long)((t + 1) * 64 + krK) * QKVW + d0K;
#pragma unroll
            for (int u = 0; u < 4; u++) kf[u] = *(const float4*)(ks + 4 * u);
            const float* vs = v + (long)((t + 1) * 64 + kr0V) * QKVW + dV;
#pragma unroll
            for (int j = 0; j < 16; j++) vf[j] = vs[(long)j * QKVW];
        }

        float s[8][4];
#pragma unroll
        for (int nf = 0; nf < 8; nf++)
#pragma unroll
            for (int c = 0; c < 4; c++) s[nf][c] = 0.f;

        const unsigned* Kb = Ks + buf * KTILE * DSTR;
#pragma unroll
        for (int blk = 0; blk < 2; blk++) {
#pragma unroll
            for (int g = 0; g < 2; g++) {
                const int off = blk * 32 + cq * 8 + 4 * g;
                uint4 aA = *(const uint4*)(Qs + (qrow0)     * DSTR + off);
                uint4 aB = *(const uint4*)(Qs + (qrow0 + 8) * DSTR + off);
#pragma unroll
                for (int nf = 0; nf < 8; nf++) {
                    uint4 bb = *(const uint4*)(Kb + (nf * 8 + r) * DSTR + off);
                    mma8(s[nf], aA.x, aB.x, aA.y, aB.y, bb.x, bb.y);
                    mma8(s[nf], aA.z, aB.z, aA.w, aB.w, bb.z, bb.w);
                }
            }
        }

#pragma unroll
        for (int nf = 0; nf < 8; nf++) {
            float e0 = __expf(s[nf][0]);
            float e1 = __expf(s[nf][1]);
            float e2 = __expf(s[nf][2]);
            float e3 = __expf(s[nf][3]);
            lp0 += e0 + e1;
            lp1 += e2 + e3;
            unsigned* pr0 = Ps + (qrow0)     * DSTR + (nf >> 2) * 32 + 2 * (nf & 3);
            unsigned* pr1 = Ps + (qrow0 + 8) * DSTR + (nf >> 2) * 32 + 2 * (nf & 3);
            pr0[pv0] = f2tf(e0); pr0[pv1] = f2tf(e1);
            pr1[pv0] = f2tf(e2); pr1[pv1] = f2tf(e3);
        }
        __syncwarp();

        const unsigned* Vb = Vs + buf * KTILE * DSTR;
#pragma unroll
        for (int blk = 0; blk < 2; blk++) {
#pragma unroll
            for (int g = 0; g < 2; g++) {
                const int off = blk * 32 + cq * 8 + 4 * g;
                uint4 aA = *(const uint4*)(Ps + (qrow0)     * DSTR + off);
                uint4 aB = *(const uint4*)(Ps + (qrow0 + 8) * DSTR + off);
#pragma unroll
                for (int nf = 0; nf < 8; nf++) {
                    uint4 bb = *(const uint4*)(Vb + (nf * 8 + r) * DSTR + off);
                    mma8(o[nf], aA.x, aB.x, aA.y, aB.y, bb.x, bb.y);
                    mma8(o[nf], aA.z, aB.z, aA.w, aB.w, bb.z, bb.w);
                }
            }
        }

        if (hasNext) {
            const int nb = buf ^ 1;
            unsigned* kd = Ks + nb * KTILE * DSTR + krK * DSTR + (d0K & 32) + 4 * ((d0K >> 4) & 1);
            const float* fk = (const float*)kf;
#pragma unroll
            for (int e = 0; e < 4; e++) {
                uint4 ss;
                ss.x = f2tf(fk[e]); ss.y = f2tf(fk[4 + e]);
                ss.z = f2tf(fk[8 + e]); ss.w = f2tf(fk[12 + e]);
                *(uint4*)(kd + e * 8) = ss;
            }
            unsigned* vd = Vs + nb * KTILE * DSTR + dV * DSTR + (kr0V & 32) + 4 * ((kr0V >> 4) & 1);
#pragma unroll
            for (int e = 0; e < 4; e++) {
                uint4 ss;
                ss.x = f2tf(vf[e]); ss.y = f2tf(vf[4 + e]);
                ss.z = f2tf(vf[8 + e]); ss.w = f2tf(vf[12 + e]);
                *(uint4*)(vd + e * 8) = ss;
            }
        }
        __syncthreads();
    }

    lp0 += __shfl_xor_sync(0xffffffffu, lp0, 1);
    lp0 += __shfl_xor_sync(0xffffffffu, lp0, 2);
    lp1 += __shfl_xor_sync(0xffffffffu, lp1, 1);
    lp1 += __shfl_xor_sync(0xffffffffu, lp1, 2);
    const float i0 = 1.f / lp0;
    const float i1 = 1.f / lp1;

    const long outRow0 = (long)(bh >> 3) * Tv + q0 + qrow0;
    const int  colB = (bh & 7) * DHv;
#pragma unroll
    for (int nf = 0; nf < 8; nf++) {
        int col = colB + nf * 8 + 2 * cq;
        float2 w0; w0.x = f2tff(o[nf][0] * i0); w0.y = f2tff(o[nf][1] * i0);
        float2 w1; w1.x = f2tff(o[nf][2] * i1); w1.y = f2tff(o[nf][3] * i1);
        *(float2*)(y + (outRow0)     * Cv + col) = w0;
        *(float2*)(y + (outRow0 + 8) * Cv + col) = w1;
    }
}

extern "C" void kernel_launch(void* const* d_in, const int* in_sizes, int n_in,
                              void* d_out, int out_size)
{
    const int*   idx   = (const int*)  d_in[0];
    const float* tok   = (const float*)d_in[1];
    const float* pos   = (const float*)d_in[2];
    const float* ln1g  = (const float*)d_in[3];
    const float* ln1b  = (const float*)d_in[4];
    const float* Wq    = (const float*)d_in[5];
    const float* bq    = (const float*)d_in[6];
    const float* Wk    = (const float*)d_in[7];
    const float* bk    = (const float*)d_in[8];
    const float* Wv    = (const float*)d_in[9];
    const float* bv    = (const float*)d_in[10];
    const float* Wp    = (const float*)d_in[11];
    const float* bp    = (const float*)d_in[12];
    const float* ln2g  = (const float*)d_in[13];
    const float* ln2b  = (const float*)d_in[14];
    const float* W1    = (const float*)d_in[15];
    const float* b1    = (const float*)d_in[16];
    const float* W2    = (const float*)d_in[17];
    const float* b2    = (const float*)d_in[18];
    const float* lnfg  = (const float*)d_in[19];
    const float* lnfb  = (const float*)d_in[20];
    const float* Whead = (const float*)d_in[21];
    float* out = (float*)d_out;

    float *x, *xn, *qkv, *y, *h, *wqkv, *bqkv, *w1t, *w2t;
    cudaGetSymbolAddress((void**)&x,    g_x);
    cudaGetSymbolAddress((void**)&xn,   g_xn);
    cudaGetSymbolAddress((void**)&qkv,  g_qkv);
    cudaGetSymbolAddress((void**)&y,    g_y);
    cudaGetSymbolAddress((void**)&h,    g_h);
    cudaGetSymbolAddress((void**)&wqkv, g_wqkv);
    cudaGetSymbolAddress((void**)&bqkv, g_bqkv);
    cudaGetSymbolAddress((void**)&w1t,  g_w1t);
    cudaGetSymbolAddress((void**)&w2t,  g_w2t);

    cudaFuncSetAttribute(gemm_tc<false>,
                         cudaFuncAttributeMaxDynamicSharedMemorySize, SMEM_BYTES);
    cudaFuncSetAttribute(gemm_ca<false, true>,
                         cudaFuncAttributeMaxDynamicSharedMemorySize, SMEM_CA_BYTES);
    cudaFuncSetAttribute(gemm_ca<true, true>,
                         cudaFuncAttributeMaxDynamicSharedMemorySize, SMEM_CA_BYTES);
    cudaFuncSetAttribute(gemm_ca<false, false>,
                         cudaFuncAttributeMaxDynamicSharedMemorySize, SMEM_CA_BYTES);
    cudaFuncSetAttribute(attn_k,
                         cudaFuncAttributeMaxDynamicSharedMemorySize, ATT_SMEM_BYTES);

    pack_w_k<<<(Lv * Cv * QKVW) / 256, 256>>>(Wq, Wk, Wv, wqkv);
    pack_b_k<<<(Lv * QKVW) / 256, 256>>>(bq, bk, bv, bqkv);
    cvt_k<<<(Lv * Cv * FFv) / 1024, 256>>>(W1, w1t);
    cvt_k<<<(Lv * FFv * Cv) / 1024, 256>>>(W2, w2t);
    embed_k<<<(MALL * Cv) / 256, 256>>>(idx, tok, pos, x);

    for (int s = 0; s < STEPS; s++) {
        for (int l = 0; l < Lv; l++) {
            const float* wqkv_l = wqkv + (long)l * Cv * QKVW;
            const float* bqkv_l = bqkv + (long)l * QKVW;
            const float* wp  = Wp  + (long)l * Cv * Cv;
            const float* w1l = w1t + (long)l * Cv * FFv;
            const float* w2l = w2t + (long)l * FFv * Cv;

            ln_k<<<MALL / 8, 256>>>(x, ln1g + l * Cv, ln1b + l * Cv, xn);

            dim3 gQKV(QKVW / BN2, MALL / BM, 1);
            gemm_ca<false, true><<<gQKV, 256, SMEM_CA_BYTES>>>(
                xn, Cv, wqkv_l, QKVW, bqkv_l, nullptr, qkv, QKVW, Cv);

            dim3 gAtt(Tv / QROWS, Bv * Hv, 1);
            attn_k<<<gAtt, 256, ATT_SMEM_BYTES>>>(qkv, y);

            dim3 gProj(Cv / BN, MALL / BM, 1);
            gemm_tc<false><<<gProj, 256, SMEM_BYTES>>>(
                y, Cv, wp, Cv, bp + l * Cv, x, x, Cv, Cv);

            ln_k<<<MALL / 8, 256>>>(x, ln2g + l * Cv, ln2b + l * Cv, xn);

            dim3 gFF1(FFv / BN2, MALL / BM, 1);
            gemm_ca<true, true><<<gFF1, 256, SMEM_CA_BYTES>>>(
                xn, Cv, w1l, FFv, b1 + l * FFv, nullptr, h, FFv, Cv);

            dim3 gFF2(Cv / BN2, MALL / BM, 1);
            gemm_ca<false, false><<<gFF2, 256, SMEM_CA_BYTES>>>(
                h, FFv, w2l, Cv, b2 + l * Cv, x, x, Cv, FFv);
        }
    }

    ln_k<<<MALL / 8, 256>>>(x, lnfg, lnfb, xn);
    dim3 gHead(Vv / BN, MALL / BM, 1);
    gemm_tc<false><<<gHead, 256, SMEM_BYTES>>>(
        xn, Cv, Whead, Vv, nullptr, nullptr, out, Vv, Cv);
}

// round 12
// speedup vs baseline: 1.6709x; 1.0206x over previous
#include <cuda_runtime.h>
#include <math.h>

#define Bv    8
#define Tv    512
#define Cv    512
#define Hv    8
#define DHv   64
#define Lv    2
#define Vv    512
#define FFv   2048
#define STEPS 4
#define MALL  (Bv*Tv)
#define SCALE 0.125f
#define QKVW  1536

#define BM 128
#define BK 32
#define ASTR (BK + 4)

#define BN2 128
#define BSTR2 (BN2 + 8)
#define NSTAGE 3
#define SMEM_CA_BYTES (NSTAGE*(BM*ASTR + BK*BSTR2)*4)   // 107520

#define QROWS 128
#define KTILE 64
#define DSTR  68
#define ATT_SMEM_BYTES ((2*QROWS*DSTR + 4*KTILE*DSTR)*4)

__device__ float g_x  [MALL*Cv];
__device__ float g_xn [MALL*Cv];
__device__ float g_qkv[MALL*QKVW];
__device__ float g_y  [MALL*Cv];
__device__ float g_h  [MALL*FFv];
__device__ float g_wqkv[Lv*Cv*QKVW];
__device__ float g_bqkv[Lv*QKVW];
__device__ float g_w1t[Lv*Cv*FFv];
__device__ float g_w2t[Lv*FFv*Cv];
__device__ float g_wpt[Lv*Cv*Cv];
__device__ float g_wht[Cv*Vv];

__device__ __forceinline__ unsigned f2tf(float f)
{
    unsigned u;
    asm("cvt.rna.tf32.f32 %0, %1;" : "=r"(u) : "f"(f));
    return u;
}
__device__ __forceinline__ float f2tff(float f)
{
    return __uint_as_float(f2tf(f));
}

__device__ __forceinline__ void mma8(float acc[4],
                                     unsigned a0, unsigned a1, unsigned a2, unsigned a3,
                                     unsigned b0, unsigned b1)
{
    asm volatile(
        "mma.sync.aligned.m16n8k8.row.col.f32.tf32.tf32.f32 "
        "{%0,%1,%2,%3}, {%4,%5,%6,%7}, {%8,%9}, {%0,%1,%2,%3};\n"
        : "+f"(acc[0]), "+f"(acc[1]), "+f"(acc[2]), "+f"(acc[3])
        : "r"(a0), "r"(a1), "r"(a2), "r"(a3), "r"(b0), "r"(b1));
}

__device__ __forceinline__ void cp16(unsigned dst, const void* src)
{
    asm volatile("cp.async.cg.shared.global [%0], [%1], 16;" :: "r"(dst), "l"(src));
}

__global__ void embed_k(const int* __restrict__ idx,
                        const float* __restrict__ tok,
                        const float* __restrict__ pos,
                        float* __restrict__ x)
{
    int i = blockIdx.x * 256 + threadIdx.x;
    int c  = i & (Cv - 1);
    int bt = i >> 9;
    int t  = bt & (Tv - 1);
    x[i] = tok[idx[bt] * Cv + c] + pos[t * Cv + c];
}

__global__ void pack_w_k(const float* __restrict__ Wq,
                         const float* __restrict__ Wk,
                         const float* __restrict__ Wv,
                         float* __restrict__ out)
{
    int i = blockIdx.x * 256 + threadIdx.x;
    int j = i % QKVW;
    int rem = i / QKVW;
    int kk = rem % Cv;
    int l  = rem / Cv;
    int sel = j >> 9, col = j & 511;
    const float* W = (sel == 0) ? Wq : (sel == 1) ? Wk : Wv;
    out[i] = f2tff(W[((long)l * Cv + kk) * Cv + col]);
}

__global__ void pack_b_k(const float* __restrict__ bq,
                         const float* __restrict__ bk,
                         const float* __restrict__ bv,
                         float* __restrict__ out)
{
    int i = blockIdx.x * 256 + threadIdx.x;
    int j = i % QKVW;
    int l = i / QKVW;
    int sel = j >> 9, col = j & 511;
    const float* bb = (sel == 0) ? bq : (sel == 1) ? bk : bv;
    out[i] = bb[l * Cv + col];
}

__global__ void cvt_k(const float* __restrict__ in, float* __restrict__ out)
{
    int i = blockIdx.x * 256 + threadIdx.x;
    float4 v = *(const float4*)(in + i * 4);
    float4 w;
    w.x = f2tff(v.x); w.y = f2tff(v.y); w.z = f2tff(v.z); w.w = f2tff(v.w);
    *(float4*)(out + i * 4) = w;
}

// ---- warp-per-row layernorm; output tf32-rounded ----
__global__ __launch_bounds__(256) void ln_k(const float* __restrict__ x,
                                            const float* __restrict__ g,
                                            const float* __restrict__ b,
                                            float* __restrict__ o)
{
    const int lane = threadIdx.x & 31;
    const int warp = threadIdx.x >> 5;
    const long row = (long)blockIdx.x * 8 + warp;
    const float* xr = x + row * Cv;

    float4 v[4];
#pragma unroll
    for (int j = 0; j < 4; j++) v[j] = *(const float4*)(xr + lane * 4 + j * 128);

    float s = 0.f, ss = 0.f;
#pragma unroll
    for (int j = 0; j < 4; j++) {
        s  += v[j].x + v[j].y + v[j].z + v[j].w;
        ss += v[j].x * v[j].x + v[j].y * v[j].y + v[j].z * v[j].z + v[j].w * v[j].w;
    }
#pragma unroll
    for (int off = 16; off > 0; off >>= 1) {
        s  += __shfl_xor_sync(0xffffffffu, s,  off);
        ss += __shfl_xor_sync(0xffffffffu, ss, off);
    }
    const float mu  = s * (1.f / Cv);
    const float var = ss * (1.f / Cv) - mu * mu;
    const float inv = rsqrtf(var + 1e-5f);

    float* orow = o + row * Cv;
#pragma unroll
    for (int j = 0; j < 4; j++) {
        const int c = lane * 4 + j * 128;
        float4 gv = *(const float4*)(g + c);
        float4 bb = *(const float4*)(b + c);
        float4 w;
        w.x = f2tff((v[j].x - mu) * inv * gv.x + bb.x);
        w.y = f2tff((v[j].y - mu) * inv * gv.y + bb.y);
        w.z = f2tff((v[j].z - mu) * inv * gv.z + bb.z);
        w.w = f2tff((v[j].w - mu) * inv * gv.w + bb.w);
        *(float4*)(orow + c) = w;
    }
}

// ---- tf32 GEMM 128x128, cp.async 3-stage, single sync/iter, pre-rounded inputs ----
template <bool GELU_ACT, bool ROUND_OUT>
__global__ __launch_bounds__(256) void gemm_ca(
    const float* __restrict__ A, int lda,
    const float* __restrict__ Bm, int ldb,
    const float* __restrict__ bias,
    const float* __restrict__ res,
    float* __restrict__ Cm, int ldc,
    int K)
{
    extern __shared__ unsigned sm_[];
    unsigned* As = sm_;                          // [NSTAGE][BM][ASTR]
    unsigned* Bs = sm_ + NSTAGE * BM * ASTR;     // [NSTAGE][BK][BSTR2]

    const int tid  = threadIdx.x;
    const int lane = tid & 31;
    const int wid  = tid >> 5;
    const int mWarp = (wid >> 1) * 32;
    const int nWarp = (wid & 1) * 64;
    const int rowBase = blockIdx.y * BM;
    const int colBase = blockIdx.x * BN2;
    const int r  = lane >> 2;
    const int cq = lane & 3;

    const unsigned smem_u32 = (unsigned)__cvta_generic_to_shared(sm_);
    const unsigned bbase = smem_u32 + NSTAGE * BM * ASTR * 4;

    float acc[2][8][4];
#pragma unroll
    for (int mi = 0; mi < 2; mi++)
#pragma unroll
        for (int ni = 0; ni < 8; ni++)
#pragma unroll
            for (int t = 0; t < 4; t++) acc[mi][ni][t] = 0.f;

    const int KT = K / BK;

#define LOAD_STAGE(s, k0)                                                        \
    {                                                                            \
        _Pragma("unroll")                                                        \
        for (int i = 0; i < 4; i++) {                                            \
            int f = tid + i * 256;                                               \
            int row = f >> 3, c4 = (f & 7) * 4;                                  \
            cp16(smem_u32 + (((s) * BM + row) * ASTR + c4) * 4,                  \
                 A + (long)(rowBase + row) * lda + (k0) + c4);                   \
        }                                                                        \
        _Pragma("unroll")                                                        \
        for (int i = 0; i < 4; i++) {                                            \
            int f = tid + i * 256;                                               \
            int kk = f >> 5, n4 = (f & 31) * 4;                                  \
            cp16(bbase + (((s) * BK + kk) * BSTR2 + n4) * 4,                     \
                 Bm + (long)((k0) + kk) * ldb + colBase + n4);                   \
        }                                                                        \
        asm volatile("cp.async.commit_group;");                                  \
    }

    LOAD_STAGE(0, 0);
    LOAD_STAGE(1, BK);

    for (int kt = 0; kt < KT; kt++) {
        if (kt + 1 < KT) asm volatile("cp.async.wait_group 1;");
        else             asm volatile("cp.async.wait_group 0;");
        __syncthreads();    // also guards buffer reuse for the load below

        const int buf = kt % NSTAGE;
        if (kt + 2 < KT) {
            const int s2 = (kt + 2) % NSTAGE;
            const int k2 = (kt + 2) * BK;
            LOAD_STAGE(s2, k2);
        }

        const unsigned* Ab = As + buf * BM * ASTR;
        const unsigned* Bb = Bs + buf * BK * BSTR2;
#pragma unroll
        for (int ks = 0; ks < 4; ks++) {
            const int kb = ks * 8;
            unsigned a[2][4];
#pragma unroll
            for (int mi = 0; mi < 2; mi++) {
                int m = mWarp + mi * 16;
                a[mi][0] = Ab[(m + r)     * ASTR + kb + cq];
                a[mi][1] = Ab[(m + r + 8) * ASTR + kb + cq];
                a[mi][2] = Ab[(m + r)     * ASTR + kb + cq + 4];
                a[mi][3] = Ab[(m + r + 8) * ASTR + kb + cq + 4];
            }
            unsigned bb[8][2];
#pragma unroll
            for (int ni = 0; ni < 8; ni++) {
                int n = nWarp + ni * 8 + r;
                bb[ni][0] = Bb[(kb + cq)     * BSTR2 + n];
                bb[ni][1] = Bb[(kb + cq + 4) * BSTR2 + n];
            }
#pragma unroll
            for (int mi = 0; mi < 2; mi++)
#pragma unroll
                for (int ni = 0; ni < 8; ni++)
                    mma8(acc[mi][ni], a[mi][0], a[mi][1], a[mi][2], a[mi][3],
                         bb[ni][0], bb[ni][1]);
        }
        // no trailing sync: next iteration's wait+sync guards buffer reuse
    }
#undef LOAD_STAGE

#pragma unroll
    for (int mi = 0; mi < 2; mi++) {
#pragma unroll
        for (int ni = 0; ni < 8; ni++) {
            int row0 = rowBase + mWarp + mi * 16 + r;
            int col  = colBase + nWarp + ni * 8 + 2 * cq;
#pragma unroll
            for (int half = 0; half < 2; half++) {
                int rr = row0 + half * 8;
                float v0 = acc[mi][ni][half * 2 + 0];
                float v1 = acc[mi][ni][half * 2 + 1];
                if (bias) { v0 += bias[col]; v1 += bias[col + 1]; }
                if (res) {
                    float2 rv = *(const float2*)(res + (long)rr * ldc + col);
                    v0 += rv.x; v1 += rv.y;
                }
                if (GELU_ACT) {
                    v0 = 0.5f * v0 * (1.f + erff(v0 * 0.70710678118654752f));
                    v1 = 0.5f * v1 * (1.f + erff(v1 * 0.70710678118654752f));
                }
                if (ROUND_OUT) { v0 = f2tff(v0); v1 = f2tff(v1); }
                float2 ov; ov.x = v0; ov.y = v1;
                *(float2*)(Cm + (long)rr * ldc + col) = ov;
            }
        }
    }
}

// ---- fused flash attention over packed QKV (inputs tf32-rounded) ----
__global__ __launch_bounds__(256) void attn_k(
    const float* __restrict__ qkv,
    float* __restrict__ y)
{
    extern __shared__ unsigned sm_[];
    unsigned* Qs = sm_;
    unsigned* Ks = Qs + QROWS * DSTR;
    unsigned* Vs = Ks + 2 * KTILE * DSTR;
    unsigned* Ps = Vs + 2 * KTILE * DSTR;

    const int tid  = threadIdx.x;
    const int lane = tid & 31;
    const int wid  = tid >> 5;
    const int r  = lane >> 2;
    const int cq = lane & 3;

    const int bh = blockIdx.y;
    const long base = (long)(bh >> 3) * Tv * QKVW + (bh & 7) * DHv;
    const float* q = qkv + base;
    const float* k = qkv + base + Cv;
    const float* v = qkv + base + 2 * Cv;
    const int q0 = blockIdx.x * QROWS;

    {
        int row = tid & 127;
        int d0  = (tid >> 7) * 32;
        const float* src = q + (long)(q0 + row) * QKVW + d0;
        float4 f[8];
#pragma unroll
        for (int u = 0; u < 8; u++) f[u] = *(const float4*)(src + 4 * u);
        unsigned* dst = Qs + row * DSTR + d0;
        const float* ff = (const float*)f;
#pragma unroll
        for (int e = 0; e < 4; e++) {
            uint4 s0, s1;
            s0.x = f2tf(ff[e] * SCALE);      s0.y = f2tf(ff[4 + e] * SCALE);
            s0.z = f2tf(ff[8 + e] * SCALE);  s0.w = f2tf(ff[12 + e] * SCALE);
            s1.x = f2tf(ff[16 + e] * SCALE); s1.y = f2tf(ff[20 + e] * SCALE);
            s1.z = f2tf(ff[24 + e] * SCALE); s1.w = f2tf(ff[28 + e] * SCALE);
            *(uint4*)(dst + e * 8)     = s0;
            *(uint4*)(dst + e * 8 + 4) = s1;
        }
    }

    const int krK = tid & 63;
    const int d0K = (tid >> 6) * 16;
    const int dV   = tid & 63;
    const int kr0V = (tid >> 6) * 16;

    float4 kf[4];
    float  vf[16];
    {
        const float* ks = k + (long)krK * QKVW + d0K;
#pragma unroll
        for (int u = 0; u < 4; u++) kf[u] = *(const float4*)(ks + 4 * u);
        const float* vs = v + (long)kr0V * QKVW + dV;
#pragma unroll
        for (int j = 0; j < 16; j++) vf[j] = vs[(long)j * QKVW];
    }
    {
        unsigned* kd = Ks + krK * DSTR + (d0K & 32) + 4 * ((d0K >> 4) & 1);
        const float* fk = (const float*)kf;
#pragma unroll
        for (int e = 0; e < 4; e++) {
            uint4 s;
            s.x = f2tf(fk[e]); s.y = f2tf(fk[4 + e]);
            s.z = f2tf(fk[8 + e]); s.w = f2tf(fk[12 + e]);
            *(uint4*)(kd + e * 8) = s;
        }
        unsigned* vd = Vs + dV * DSTR + (kr0V & 32) + 4 * ((kr0V >> 4) & 1);
#pragma unroll
        for (int e = 0; e < 4; e++) {
            uint4 s;
            s.x = f2tf(vf[e]); s.y = f2tf(vf[4 + e]);
            s.z = f2tf(vf[8 + e]); s.w = f2tf(vf[12 + e]);
            *(uint4*)(vd + e * 8) = s;
        }
    }
    __syncthreads();

    float o[8][4];
#pragma unroll
    for (int nf = 0; nf < 8; nf++)
#pragma unroll
        for (int t = 0; t < 4; t++) o[nf][t] = 0.f;
    float lp0 = 0.f, lp1 = 0.f;

    const int v0i = 2 * cq, v1i = 2 * cq + 1;
    const int pv0 = (v0i & 3) * 8 + (v0i >> 2);
    const int pv1 = (v1i & 3) * 8 + (v1i >> 2);
    const int qrow0 = wid * 16 + r;

    for (int t = 0; t < 8; t++) {
        const int buf = t & 1;
        const bool hasNext = (t < 7);

        if (hasNext) {
            const float* ks = k + (long)((t + 1) * 64 + krK) * QKVW + d0K;
#pragma unroll
            for (int u = 0; u < 4; u++) kf[u] = *(const float4*)(ks + 4 * u);
            const float* vs = v + (long)((t + 1) * 64 + kr0V) * QKVW + dV;
#pragma unroll
            for (int j = 0; j < 16; j++) vf[j] = vs[(long)j * QKVW];
        }

        float s[8][4];
#pragma unroll
        for (int nf = 0; nf < 8; nf++)
#pragma unroll
            for (int c = 0; c < 4; c++) s[nf][c] = 0.f;

        const unsigned* Kb = Ks + buf * KTILE * DSTR;
#pragma unroll
        for (int blk = 0; blk < 2; blk++) {
#pragma unroll
            for (int g = 0; g < 2; g++) {
                const int off = blk * 32 + cq * 8 + 4 * g;
                uint4 aA = *(const uint4*)(Qs + (qrow0)     * DSTR + off);
                uint4 aB = *(const uint4*)(Qs + (qrow0 + 8) * DSTR + off);
#pragma unroll
                for (int nf = 0; nf < 8; nf++) {
                    uint4 bb = *(const uint4*)(Kb + (nf * 8 + r) * DSTR + off);
                    mma8(s[nf], aA.x, aB.x, aA.y, aB.y, bb.x, bb.y);
                    mma8(s[nf], aA.z, aB.z, aA.w, aB.w, bb.z, bb.w);
                }
            }
        }

#pragma unroll
        for (int nf = 0; nf < 8; nf++) {
            float e0 = __expf(s[nf][0]);
            float e1 = __expf(s[nf][1]);
            float e2 = __expf(s[nf][2]);
            float e3 = __expf(s[nf][3]);
            lp0 += e0 + e1;
            lp1 += e2 + e3;
            unsigned* pr0 = Ps + (qrow0)     * DSTR + (nf >> 2) * 32 + 2 * (nf & 3);
            unsigned* pr1 = Ps + (qrow0 + 8) * DSTR + (nf >> 2) * 32 + 2 * (nf & 3);
            pr0[pv0] = f2tf(e0); pr0[pv1] = f2tf(e1);
            pr1[pv0] = f2tf(e2); pr1[pv1] = f2tf(e3);
        }
        __syncwarp();

        const unsigned* Vb = Vs + buf * KTILE * DSTR;
#pragma unroll
        for (int blk = 0; blk < 2; blk++) {
#pragma unroll
            for (int g = 0; g < 2; g++) {
                const int off = blk * 32 + cq * 8 + 4 * g;
                uint4 aA = *(const uint4*)(Ps + (qrow0)     * DSTR + off);
                uint4 aB = *(const uint4*)(Ps + (qrow0 + 8) * DSTR + off);
#pragma unroll
                for (int nf = 0; nf < 8; nf++) {
                    uint4 bb = *(const uint4*)(Vb + (nf * 8 + r) * DSTR + off);
                    mma8(o[nf], aA.x, aB.x, aA.y, aB.y, bb.x, bb.y);
                    mma8(o[nf], aA.z, aB.z, aA.w, aB.w, bb.z, bb.w);
                }
            }
        }

        if (hasNext) {
            const int nb = buf ^ 1;
            unsigned* kd = Ks + nb * KTILE * DSTR + krK * DSTR + (d0K & 32) + 4 * ((d0K >> 4) & 1);
            const float* fk = (const float*)kf;
#pragma unroll
            for (int e = 0; e < 4; e++) {
                uint4 ss;
                ss.x = f2tf(fk[e]); ss.y = f2tf(fk[4 + e]);
                ss.z = f2tf(fk[8 + e]); ss.w = f2tf(fk[12 + e]);
                *(uint4*)(kd + e * 8) = ss;
            }
            unsigned* vd = Vs + nb * KTILE * DSTR + dV * DSTR + (kr0V & 32) + 4 * ((kr0V >> 4) & 1);
#pragma unroll
            for (int e = 0; e < 4; e++) {
                uint4 ss;
                ss.x = f2tf(vf[e]); ss.y = f2tf(vf[4 + e]);
                ss.z = f2tf(vf[8 + e]); ss.w = f2tf(vf[12 + e]);
                *(uint4*)(vd + e * 8) = ss;
            }
        }
        __syncthreads();
    }

    lp0 += __shfl_xor_sync(0xffffffffu, lp0, 1);
    lp0 += __shfl_xor_sync(0xffffffffu, lp0, 2);
    lp1 += __shfl_xor_sync(0xffffffffu, lp1, 1);
    lp1 += __shfl_xor_sync(0xffffffffu, lp1, 2);
    const float i0 = 1.f / lp0;
    const float i1 = 1.f / lp1;

    const long outRow0 = (long)(bh >> 3) * Tv + q0 + qrow0;
    const int  colB = (bh & 7) * DHv;
#pragma unroll
    for (int nf = 0; nf < 8; nf++) {
        int col = colB + nf * 8 + 2 * cq;
        float2 w0; w0.x = f2tff(o[nf][0] * i0); w0.y = f2tff(o[nf][1] * i0);
        float2 w1; w1.x = f2tff(o[nf][2] * i1); w1.y = f2tff(o[nf][3] * i1);
        *(float2*)(y + (outRow0)     * Cv + col) = w0;
        *(float2*)(y + (outRow0 + 8) * Cv + col) = w1;
    }
}

extern "C" void kernel_launch(void* const* d_in, const int* in_sizes, int n_in,
                              void* d_out, int out_size)
{
    const int*   idx   = (const int*)  d_in[0];
    const float* tok   = (const float*)d_in[1];
    const float* pos   = (const float*)d_in[2];
    const float* ln1g  = (const float*)d_in[3];
    const float* ln1b  = (const float*)d_in[4];
    const float* Wq    = (const float*)d_in[5];
    const float* bq    = (const float*)d_in[6];
    const float* Wk    = (const float*)d_in[7];
    const float* bk    = (const float*)d_in[8];
    const float* Wv    = (const float*)d_in[9];
    const float* bv    = (const float*)d_in[10];
    const float* Wp    = (const float*)d_in[11];
    const float* bp    = (const float*)d_in[12];
    const float* ln2g  = (const float*)d_in[13];
    const float* ln2b  = (const float*)d_in[14];
    const float* W1    = (const float*)d_in[15];
    const float* b1    = (const float*)d_in[16];
    const float* W2    = (const float*)d_in[17];
    const float* b2    = (const float*)d_in[18];
    const float* lnfg  = (const float*)d_in[19];
    const float* lnfb  = (const float*)d_in[20];
    const float* Whead = (const float*)d_in[21];
    float* out = (float*)d_out;

    float *x, *xn, *qkv, *y, *h, *wqkv, *bqkv, *w1t, *w2t, *wpt, *wht;
    cudaGetSymbolAddress((void**)&x,    g_x);
    cudaGetSymbolAddress((void**)&xn,   g_xn);
    cudaGetSymbolAddress((void**)&qkv,  g_qkv);
    cudaGetSymbolAddress((void**)&y,    g_y);
    cudaGetSymbolAddress((void**)&h,    g_h);
    cudaGetSymbolAddress((void**)&wqkv, g_wqkv);
    cudaGetSymbolAddress((void**)&bqkv, g_bqkv);
    cudaGetSymbolAddress((void**)&w1t,  g_w1t);
    cudaGetSymbolAddress((void**)&w2t,  g_w2t);
    cudaGetSymbolAddress((void**)&wpt,  g_wpt);
    cudaGetSymbolAddress((void**)&wht,  g_wht);

    cudaFuncSetAttribute(gemm_ca<false, true>,
                         cudaFuncAttributeMaxDynamicSharedMemorySize, SMEM_CA_BYTES);
    cudaFuncSetAttribute(gemm_ca<true, true>,
                         cudaFuncAttributeMaxDynamicSharedMemorySize, SMEM_CA_BYTES);
    cudaFuncSetAttribute(gemm_ca<false, false>,
                         cudaFuncAttributeMaxDynamicSharedMemorySize, SMEM_CA_BYTES);
    cudaFuncSetAttribute(attn_k,
                         cudaFuncAttributeMaxDynamicSharedMemorySize, ATT_SMEM_BYTES);

    pack_w_k<<<(Lv * Cv * QKVW) / 256, 256>>>(Wq, Wk, Wv, wqkv);
    pack_b_k<<<(Lv * QKVW) / 256, 256>>>(bq, bk, bv, bqkv);
    cvt_k<<<(Lv * Cv * FFv) / 1024, 256>>>(W1, w1t);
    cvt_k<<<(Lv * FFv * Cv) / 1024, 256>>>(W2, w2t);
    cvt_k<<<(Lv * Cv * Cv) / 1024, 256>>>(Wp, wpt);
    cvt_k<<<(Cv * Vv) / 1024, 256>>>(Whead, wht);
    embed_k<<<(MALL * Cv) / 256, 256>>>(idx, tok, pos, x);

    for (int s = 0; s < STEPS; s++) {
        for (int l = 0; l < Lv; l++) {
            const float* wqkv_l = wqkv + (long)l * Cv * QKVW;
            const float* bqkv_l = bqkv + (long)l * QKVW;
            const float* wpl = wpt + (long)l * Cv * Cv;
            const float* w1l = w1t + (long)l * Cv * FFv;
            const float* w2l = w2t + (long)l * FFv * Cv;

            ln_k<<<MALL / 8, 256>>>(x, ln1g + l * Cv, ln1b + l * Cv, xn);

            dim3 gQKV(QKVW / BN2, MALL / BM, 1);
            gemm_ca<false, true><<<gQKV, 256, SMEM_CA_BYTES>>>(
                xn, Cv, wqkv_l, QKVW, bqkv_l, nullptr, qkv, QKVW, Cv);

            dim3 gAtt(Tv / QROWS, Bv * Hv, 1);
            attn_k<<<gAtt, 256, ATT_SMEM_BYTES>>>(qkv, y);

            dim3 gProj(Cv / BN2, MALL / BM, 1);
            gemm_ca<false, false><<<gProj, 256, SMEM_CA_BYTES>>>(
                y, Cv, wpl, Cv, bp + l * Cv, x, x, Cv, Cv);

            ln_k<<<MALL / 8, 256>>>(x, ln2g + l * Cv, ln2b + l * Cv, xn);

            dim3 gFF1(FFv / BN2, MALL / BM, 1);
            gemm_ca<true, true><<<gFF1, 256, SMEM_CA_BYTES>>>(
                xn, Cv, w1l, FFv, b1 + l * FFv, nullptr, h, FFv, Cv);

            dim3 gFF2(Cv / BN2, MALL / BM, 1);
            gemm_ca<false, false><<<gFF2, 256, SMEM_CA_BYTES>>>(
                h, FFv, w2l, Cv, b2 + l * Cv, x, x, Cv, FFv);
        }
    }

    ln_k<<<MALL / 8, 256>>>(x, lnfg, lnfb, xn);
    dim3 gHead(Vv / BN2, MALL / BM, 1);
    gemm_ca<false, false><<<gHead, 256, SMEM_CA_BYTES>>>(
        xn, Cv, wht, Vv, nullptr, nullptr, out, Vv, Cv);
}